// round 11
// baseline (speedup 1.0000x reference)
#include <cuda_runtime.h>
#include <cuda_fp16.h>
#include <cstdint>
#include <math.h>

#define B_ 128
#define T_ 64
#define E_ 2048
#define H_ 1024
#define R_ 8
#define H3 3072

// ==================== helpers (baseline PTX only) ====================
__device__ __forceinline__ uint32_t smem_to_u32(const void* p) {
    uint32_t a;
    asm("{ .reg .u64 t; cvta.to.shared.u64 t, %1; cvt.u32.u64 %0, t; }"
        : "=r"(a) : "l"(p));
    return a;
}
__device__ __forceinline__ uint32_t swz(uint32_t b) { return b ^ ((b >> 3) & 0x70); }

__device__ __forceinline__ void cpa16(uint32_t dst, const void* src) {
    asm volatile("cp.async.cg.shared.global [%0], [%1], 16;" :: "r"(dst), "l"(src));
}
__device__ __forceinline__ void ldm_x4(uint32_t* r, uint32_t a) {
    asm volatile("ldmatrix.sync.aligned.m8n8.x4.shared.b16 {%0,%1,%2,%3}, [%4];"
                 : "=r"(r[0]), "=r"(r[1]), "=r"(r[2]), "=r"(r[3]) : "r"(a));
}
__device__ __forceinline__ void mma16816(float* c, const uint32_t* a, const uint32_t* b) {
    asm volatile(
        "mma.sync.aligned.m16n8k16.row.col.f32.f16.f16.f32 "
        "{%0,%1,%2,%3}, {%4,%5,%6,%7}, {%8,%9}, {%0,%1,%2,%3};"
        : "+f"(c[0]), "+f"(c[1]), "+f"(c[2]), "+f"(c[3])
        : "r"(a[0]), "r"(a[1]), "r"(a[2]), "r"(a[3]), "r"(b[0]), "r"(b[1]));
}

// ==================== scratch (static device, allocation-free) ====================
// GI arrays are T-MAJOR: row index = t*B + b
__device__ float d_GI_s[(size_t)B_ * T_ * H3];
__device__ float d_GI_a[(size_t)B_ * T_ * H3];
__device__ float d_GI_o[(size_t)B_ * T_ * H3];
__device__ float d_G[1280 * H3];
__device__ int d_bar;   // monotonic software grid barrier (reset each replay)

__device__ __half d_enc_h[(size_t)B_ * T_ * E_];  // row = b*T + t (input layout)
__device__ __half d_S_h[(size_t)B_ * R_ * H_];

// W images (fp16). Per ntile (128 n-rows) per k64 chunk: a 16KB SW128 tile.
__device__ __align__(16) __half d_img_hh_s[3072 * 1024];
__device__ __align__(16) __half d_img_hh_a[3072 * 1024];
__device__ __align__(16) __half d_img_hh_o[3072 * 1024];
__device__ __align__(16) __half d_img_ihE_s[3072 * 2048];
__device__ __align__(16) __half d_img_ihE_a[3072 * 2048];
__device__ __align__(16) __half d_img_ihE_o[3072 * 2048];
__device__ __align__(16) __half d_img_ihH_s[3072 * 1024];
__device__ __align__(16) __half d_img_ihH_a[3072 * 1024];

// ==================== conversion kernels ====================
__global__ void conv_enc(const float* __restrict__ enc) {
    size_t idx = (size_t)blockIdx.x * 256 + threadIdx.x;
    d_enc_h[idx] = __float2half_rn(enc[idx]);
}

__device__ __forceinline__ size_t wimg_off(int n, int k, int kwc) {
    int nt = n >> 7, r = n & 127;
    int cc = k >> 6, j = k & 63;
    uint32_t byte = (uint32_t)((r << 7) + (j << 1));
    return (((size_t)(nt * kwc + cc)) << 13) + (swz(byte) >> 1);
}

__global__ void conv_all(const float* __restrict__ ws_hh, const float* __restrict__ wa_hh,
                         const float* __restrict__ wo_hh, const float* __restrict__ ws_ih,
                         const float* __restrict__ wa_ih, const float* __restrict__ wo_ih) {
    int z = blockIdx.z;
    const float* src;
    __half* img;
    int ld, off, kb;
    switch (z) {
        case 0: src = ws_hh; img = d_img_hh_s;  ld = 1024; off = 0;    kb = 10; break;
        case 1: src = wa_hh; img = d_img_hh_a;  ld = 1024; off = 0;    kb = 10; break;
        case 2: src = wo_hh; img = d_img_hh_o;  ld = 1024; off = 0;    kb = 10; break;
        case 3: src = ws_ih; img = d_img_ihE_s; ld = 3072; off = 0;    kb = 11; break;
        case 4: src = wa_ih; img = d_img_ihE_a; ld = 3072; off = 0;    kb = 11; break;
        case 5: src = wo_ih; img = d_img_ihE_o; ld = 2048; off = 0;    kb = 11; break;
        case 6: src = ws_ih; img = d_img_ihH_s; ld = 3072; off = 2048; kb = 10; break;
        default: src = wa_ih; img = d_img_ihH_a; ld = 3072; off = 2048; kb = 10; break;
    }
    size_t idx = (size_t)blockIdx.x * 256 + threadIdx.x;
    if (idx >= ((size_t)3072 << kb)) return;
    int n = (int)(idx >> kb);
    int k = (int)(idx & ((1 << kb) - 1));
    float x = src[(size_t)n * ld + off + k];
    img[wimg_off(n, k, 1 << (kb - 6))] = __float2half_rn(x);
}

// ==================== GEMM core: 128x128 tile, k64 chunks, 3-stage ====================
static constexpr int STAGE = 32768;                  // A 16K + W 16K
static constexpr int SMEM_TOTAL = 1024 + 3 * STAGE;  // 99328

__device__ __forceinline__ void load_stage(uint32_t st, const __half* __restrict__ Ah,
                                           int astride, const int* __restrict__ rowmap,
                                           int koff, const __half* __restrict__ Wchunk,
                                           int tid) {
#pragma unroll
    for (int i = 0; i < 4; i++) {
        int lin = tid + (i << 8);
        int row = lin >> 3, seg = lin & 7;
        uint32_t so = swz((uint32_t)((row << 7) + (seg << 4)));
        cpa16(st + so, Ah + (size_t)rowmap[row] * astride + koff + (seg << 3));
    }
    const char* ws = (const char*)Wchunk;
#pragma unroll
    for (int i = 0; i < 4; i++) {
        uint32_t o = (uint32_t)((tid + (i << 8)) << 4);
        cpa16(st + 16384 + o, ws + o);
    }
    asm volatile("cp.async.commit_group;" ::: "memory");
}

// C(128x128) = Arows(128 x K) * W(128 x K)^T, single-pass fp16
__device__ void tc_gemm(const __half* __restrict__ Ah, int astride, int kchunks,
                        const __half* __restrict__ Wimg,  // pre-offset to this ntile
                        const int* __restrict__ rowmap, float* __restrict__ Cmn) {
    extern __shared__ char smem[];
    uint32_t sb = smem_to_u32(smem) + 1024;
    const int tid = threadIdx.x;
    const int wid = tid >> 5;
    const int lid = tid & 31;
    const int wm = (wid >> 2) << 6;  // 0 or 64
    const int wn = (wid & 3) << 5;   // 0,32,64,96

    const int a_r = (lid & 7) | (((lid >> 3) & 1) << 3);
    const int a_kb = ((lid >> 4) & 1) << 4;
    const int w_r = (lid & 7) | (((lid >> 4) & 1) << 3);
    const int w_kb = ((lid >> 3) & 1) << 4;

    float acc[4][4][4];
#pragma unroll
    for (int i = 0; i < 4; i++)
#pragma unroll
        for (int j = 0; j < 4; j++)
#pragma unroll
            for (int q = 0; q < 4; q++) acc[i][j][q] = 0.f;

#pragma unroll
    for (int c = 0; c < 2; c++)
        if (c < kchunks)
            load_stage(sb + c * STAGE, Ah, astride, rowmap, c << 6,
                       Wimg + ((size_t)c << 13), tid);

    int stage = 0;
    for (int c = 0; c < kchunks; c++) {
        if (c + 1 < kchunks) asm volatile("cp.async.wait_group 1;" ::: "memory");
        else                 asm volatile("cp.async.wait_group 0;" ::: "memory");
        __syncthreads();
        if (c + 2 < kchunks) {
            int ns = stage + 2;
            if (ns >= 3) ns -= 3;
            load_stage(sb + ns * STAGE, Ah, astride, rowmap, (c + 2) << 6,
                       Wimg + ((size_t)(c + 2) << 13), tid);
        }
        uint32_t stA = sb + stage * STAGE;
        uint32_t stW = stA + 16384;
#pragma unroll
        for (int ks = 0; ks < 4; ks++) {
            uint32_t wf[8];
#pragma unroll
            for (int p = 0; p < 2; p++) {
                uint32_t rowb = (uint32_t)((wn + (p << 4) + w_r) << 7);
                ldm_x4(wf + (p << 2), stW + swz(rowb + (ks << 5) + w_kb));
            }
#pragma unroll
            for (int mt = 0; mt < 4; mt++) {
                uint32_t af[4];
                uint32_t rowb = (uint32_t)((wm + (mt << 4) + a_r) << 7);
                ldm_x4(af, stA + swz(rowb + (ks << 5) + a_kb));
#pragma unroll
                for (int nt = 0; nt < 4; nt++)
                    mma16816(acc[mt][nt], af, wf + (nt << 1));
            }
        }
        if (++stage >= 3) stage = 0;
    }

    // epilogue
    const int mrow = lid >> 2;
    const int ncol = (lid & 3) << 1;
#pragma unroll
    for (int mt = 0; mt < 4; mt++) {
#pragma unroll
        for (int nt = 0; nt < 4; nt++) {
            float* c0 = Cmn + (size_t)(wm + (mt << 4) + mrow) * H3 + wn + (nt << 3) + ncol;
            *(float2*)c0 = make_float2(acc[mt][nt][0], acc[mt][nt][1]);
            *(float2*)(c0 + 8 * H3) = make_float2(acc[mt][nt][2], acc[mt][nt][3]);
        }
    }
}

// ==================== pre GEMM (timesteps [tbase, tbase+4)) ====================
// GI row for (t, b) = t*B + b; A row in d_enc_h for (t, b) = b*T + t
__global__ __launch_bounds__(256, 2) void pre_gemm_k(int tbase) {
    __shared__ int rowmap[128];
    int t = tbase + blockIdx.y;
    if (threadIdx.x < 128) rowmap[threadIdx.x] = threadIdx.x * T_ + t;
    __syncthreads();
    const __half* img;
    float* C;
    if (blockIdx.z == 0)      { img = d_img_ihE_s; C = d_GI_s; }
    else if (blockIdx.z == 1) { img = d_img_ihE_a; C = d_GI_a; }
    else                      { img = d_img_ihE_o; C = d_GI_o; }
    int nt = blockIdx.x;
    size_t woff = (size_t)nt * 32 * 8192;  // 32 k64-chunks per 128-col ntile
    tc_gemm(d_enc_h, E_, 32, img + woff, rowmap,
            C + ((size_t)t * B_) * H3 + nt * 128);
}

// ==================== FUSED step: GEMM + grid barrier + pointwise ====================
// virtual row layout in d_G (1280 rows x 3072):
//   [0,128) spk gh | [128,256) adr gh | [256,1024) oth gh |
//   [1024,1152) spk ih-state | [1152,1280) adr ih-state
__global__ __launch_bounds__(256, 2) void step_fused_k(
    const int* __restrict__ dig, int t, float* __restrict__ A,
    const float* __restrict__ bih_s, const float* __restrict__ bhh_s,
    const float* __restrict__ bih_a, const float* __restrict__ bhh_a,
    const float* __restrict__ bih_o, const float* __restrict__ bhh_o) {
    __shared__ int rowmap[128];
    int my = blockIdx.y;
    int m0 = my << 7;
    if (threadIdx.x < 128) {
        int i = threadIdx.x;
        int m = m0 + i;
        int b, role;
        if (m < 256 || m >= 1024) {
            b = i;
            int which = (my == 0) ? 0 : (my == 1) ? 1 : (my == 8) ? 1 : 0;
            role = dig[((size_t)(b * T_ + t)) * 2 + which];
        } else {
            int idx = m - 256;
            b = idx / 6;
            int k = idx % 6;
            int spk = dig[((size_t)(b * T_ + t)) * 2];
            int adr = dig[((size_t)(b * T_ + t)) * 2 + 1];
            int cnt = 0;
            role = 0;
#pragma unroll
            for (int rr = 0; rr < R_; rr++) {
                if (rr != spk && rr != adr) {
                    if (cnt == k) role = rr;
                    cnt++;
                }
            }
        }
        rowmap[i] = (b << 3) + role;
    }
    __syncthreads();
    const __half* img;
    if (my == 0)      img = d_img_hh_s;
    else if (my == 1) img = d_img_hh_a;
    else if (my < 8)  img = d_img_hh_o;
    else if (my == 8) img = d_img_ihH_s;
    else              img = d_img_ihH_a;
    int ntile = blockIdx.x;
    size_t woff = (size_t)ntile * 16 * 8192;  // 16 k64-chunks per ntile
    tc_gemm(d_S_h, H_, 16, img + woff, rowmap, d_G + (size_t)m0 * H3 + ntile * 128);

    // ---- software grid barrier (monotonic counter; safe: pre CTAs always drain) ----
    __threadfence();
    __syncthreads();
    if (threadIdx.x == 0) {
        atomicAdd(&d_bar, 1);
        int target = 240 * (t + 1);
        while (*(volatile int*)&d_bar < target) __nanosleep(64);
    }
    __syncthreads();
    __threadfence();

    // ---- phase 2: pointwise GRU update over all (b,r,h), grid-stride float4 ----
    int cta = blockIdx.y * gridDim.x + blockIdx.x;       // 0..239
    int gtid = cta * 256 + threadIdx.x;                  // 0..61439
    for (int i4 = gtid; i4 < (B_ * R_ * H_) / 4; i4 += 240 * 256) {
        int idx = i4 << 2;
        int h = idx & (H_ - 1);
        int br = idx >> 10;
        int r = br & 7, b = br >> 3;
        int spk = dig[((size_t)(b * T_ + t)) * 2];
        int adr = dig[((size_t)(b * T_ + t)) * 2 + 1];
        const float *GI, *gihs = nullptr, *bih, *bhh;
        int ghrow;
        if (r == spk) {
            ghrow = b; gihs = d_G + (size_t)(1024 + b) * H3;
            GI = d_GI_s; bih = bih_s; bhh = bhh_s;
        } else if (r == adr) {
            ghrow = 128 + b; gihs = d_G + (size_t)(1152 + b) * H3;
            GI = d_GI_a; bih = bih_a; bhh = bhh_a;
        } else {
            int k = r - (spk < r ? 1 : 0) - (adr < r ? 1 : 0);
            ghrow = 256 + b * 6 + k;
            GI = d_GI_o; bih = bih_o; bhh = bhh_o;
        }
        const float* gi = GI + ((size_t)t * B_ + b) * H3 + h;  // t-major GI
        const float* gh = d_G + (size_t)ghrow * H3 + h;
        float4 gir = *(const float4*)(gi);
        float4 giz = *(const float4*)(gi + H_);
        float4 gin = *(const float4*)(gi + 2 * H_);
        if (gihs) {
            const float* gs = gihs + h;
            float4 s0 = *(const float4*)(gs);
            float4 s1 = *(const float4*)(gs + H_);
            float4 s2 = *(const float4*)(gs + 2 * H_);
            gir.x += s0.x; gir.y += s0.y; gir.z += s0.z; gir.w += s0.w;
            giz.x += s1.x; giz.y += s1.y; giz.z += s1.z; giz.w += s1.w;
            gin.x += s2.x; gin.y += s2.y; gin.z += s2.z; gin.w += s2.w;
        }
        float4 ghr = *(const float4*)(gh);
        float4 ghz = *(const float4*)(gh + H_);
        float4 ghn = *(const float4*)(gh + 2 * H_);
        float4 b0 = *(const float4*)(bih + h);
        float4 b1 = *(const float4*)(bih + H_ + h);
        float4 b2 = *(const float4*)(bih + 2 * H_ + h);
        float4 c0 = *(const float4*)(bhh + h);
        float4 c1 = *(const float4*)(bhh + H_ + h);
        float4 c2 = *(const float4*)(bhh + 2 * H_ + h);
        float4 hold = *(const float4*)(A + idx);
        float out[4];
        __half outh[4];
#pragma unroll
        for (int q = 0; q < 4; q++) {
            float vr = ((&gir.x)[q] + (&b0.x)[q]) + ((&ghr.x)[q] + (&c0.x)[q]);
            float vz = ((&giz.x)[q] + (&b1.x)[q]) + ((&ghz.x)[q] + (&c1.x)[q]);
            float hn = (&ghn.x)[q] + (&c2.x)[q];
            float rg = 1.f / (1.f + expf(-vr));
            float zg = 1.f / (1.f + expf(-vz));
            float ng = tanhf((&gin.x)[q] + (&b2.x)[q] + rg * hn);
            float nv = (1.f - zg) * ng + zg * (&hold.x)[q];
            out[q] = nv;
            outh[q] = __float2half_rn(nv);
        }
        *(float4*)(A + idx) = make_float4(out[0], out[1], out[2], out[3]);
        *(uint2*)(&d_S_h[idx]) = *(uint2*)outh;
    }
}

static void* sym_addr(const void* sym) {
    void* p = nullptr;
    cudaGetSymbolAddress(&p, sym);
    return p;
}

extern "C" void kernel_launch(void* const* d_in, const int* in_sizes, int n_in,
                              void* d_out, int out_size) {
    (void)in_sizes; (void)n_in; (void)out_size;
    const float* enc    = (const float*)d_in[0];
    const int*   dig    = (const int*)d_in[1];
    const float* ws_ih  = (const float*)d_in[2];
    const float* ws_hh  = (const float*)d_in[3];
    const float* ws_bih = (const float*)d_in[4];
    const float* ws_bhh = (const float*)d_in[5];
    const float* wa_ih  = (const float*)d_in[6];
    const float* wa_hh  = (const float*)d_in[7];
    const float* wa_bih = (const float*)d_in[8];
    const float* wa_bhh = (const float*)d_in[9];
    const float* wo_ih  = (const float*)d_in[10];
    const float* wo_hh  = (const float*)d_in[11];
    const float* wo_bih = (const float*)d_in[12];
    const float* wo_bhh = (const float*)d_in[13];
    float* A = (float*)d_out;

    // one-time resources (created on the non-captured correctness call)
    static bool init = false;
    static cudaStream_t s2;                // LOW priority: precompute
    static cudaEvent_t evFork, evPre[16];
    if (!init) {
        int loPri = 0, hiPri = 0;
        cudaDeviceGetStreamPriorityRange(&loPri, &hiPri);
        cudaStreamCreateWithPriority(&s2, cudaStreamNonBlocking, loPri);
        cudaEventCreateWithFlags(&evFork, cudaEventDisableTiming);
        for (int i = 0; i < 16; i++)
            cudaEventCreateWithFlags(&evPre[i], cudaEventDisableTiming);
        cudaFuncSetAttribute(pre_gemm_k, cudaFuncAttributeMaxDynamicSharedMemorySize,
                             SMEM_TOTAL);
        cudaFuncSetAttribute(step_fused_k, cudaFuncAttributeMaxDynamicSharedMemorySize,
                             SMEM_TOTAL);
        init = true;
    }

    cudaMemsetAsync(d_out, 0, (size_t)B_ * R_ * H_ * sizeof(float), 0);
    cudaMemsetAsync(sym_addr(d_S_h), 0, (size_t)B_ * R_ * H_ * 2, 0);
    cudaMemsetAsync(sym_addr(&d_bar), 0, sizeof(int), 0);

    conv_enc<<<(int)((size_t)B_ * T_ * E_ / 256), 256>>>(enc);
    conv_all<<<dim3(24576, 1, 8), 256>>>(ws_hh, wa_hh, wo_hh, ws_ih, wa_ih, wo_ih);

    // fork: 16 pre batches of 4 timesteps (288 CTAs) on low-priority stream
    cudaEventRecord(evFork, 0);
    cudaStreamWaitEvent(s2, evFork, 0);
    for (int i = 0; i < 16; i++) {
        pre_gemm_k<<<dim3(24, 4, 3), 256, SMEM_TOTAL, s2>>>(i * 4);
        cudaEventRecord(evPre[i], s2);
    }

    // sequential scan: ONE fused kernel per step (GEMM + barrier + pointwise)
    for (int t = 0; t < T_; t++) {
        if ((t & 3) == 0) cudaStreamWaitEvent(0, evPre[t >> 2], 0);
        step_fused_k<<<dim3(24, 10), 256, SMEM_TOTAL>>>(
            dig, t, A, ws_bih, ws_bhh, wa_bih, wa_bhh, wo_bih, wo_bhh);
    }
}

// round 12
// speedup vs baseline: 1.1543x; 1.1543x over previous
#include <cuda_runtime.h>
#include <cuda_fp16.h>
#include <cstdint>
#include <math.h>

#define B_ 128
#define T_ 64
#define E_ 2048
#define H_ 1024
#define R_ 8
#define H3 3072

// ==================== helpers (baseline PTX only) ====================
__device__ __forceinline__ uint32_t smem_to_u32(const void* p) {
    uint32_t a;
    asm("{ .reg .u64 t; cvta.to.shared.u64 t, %1; cvt.u32.u64 %0, t; }"
        : "=r"(a) : "l"(p));
    return a;
}
__device__ __forceinline__ uint32_t swz(uint32_t b) { return b ^ ((b >> 3) & 0x70); }

__device__ __forceinline__ void cpa16(uint32_t dst, const void* src) {
    asm volatile("cp.async.cg.shared.global [%0], [%1], 16;" :: "r"(dst), "l"(src));
}
__device__ __forceinline__ void ldm_x4(uint32_t* r, uint32_t a) {
    asm volatile("ldmatrix.sync.aligned.m8n8.x4.shared.b16 {%0,%1,%2,%3}, [%4];"
                 : "=r"(r[0]), "=r"(r[1]), "=r"(r[2]), "=r"(r[3]) : "r"(a));
}
__device__ __forceinline__ void mma16816(float* c, const uint32_t* a, const uint32_t* b) {
    asm volatile(
        "mma.sync.aligned.m16n8k16.row.col.f32.f16.f16.f32 "
        "{%0,%1,%2,%3}, {%4,%5,%6,%7}, {%8,%9}, {%0,%1,%2,%3};"
        : "+f"(c[0]), "+f"(c[1]), "+f"(c[2]), "+f"(c[3])
        : "r"(a[0]), "r"(a[1]), "r"(a[2]), "r"(a[3]), "r"(b[0]), "r"(b[1]));
}
// PDL device controls (baseline PTX, sm_90+)
__device__ __forceinline__ void pdl_trigger() {
    asm volatile("griddepcontrol.launch_dependents;" ::: "memory");
}
__device__ __forceinline__ void pdl_wait() {
    asm volatile("griddepcontrol.wait;" ::: "memory");
}

// ==================== scratch (static device, allocation-free) ====================
// GI arrays are T-MAJOR: row index = t*B + b
__device__ float d_GI_s[(size_t)B_ * T_ * H3];
__device__ float d_GI_a[(size_t)B_ * T_ * H3];
__device__ float d_GI_o[(size_t)B_ * T_ * H3];
__device__ float d_G[1280 * H3];

__device__ __half d_enc_h[(size_t)B_ * T_ * E_];  // row = b*T + t (input layout)
__device__ __half d_S_h[(size_t)B_ * R_ * H_];

// W images (fp16). Per ntile (128 n-rows) per k64 chunk: a 16KB SW128 tile.
__device__ __align__(16) __half d_img_hh_s[3072 * 1024];
__device__ __align__(16) __half d_img_hh_a[3072 * 1024];
__device__ __align__(16) __half d_img_hh_o[3072 * 1024];
__device__ __align__(16) __half d_img_ihE_s[3072 * 2048];
__device__ __align__(16) __half d_img_ihE_a[3072 * 2048];
__device__ __align__(16) __half d_img_ihE_o[3072 * 2048];
__device__ __align__(16) __half d_img_ihH_s[3072 * 1024];
__device__ __align__(16) __half d_img_ihH_a[3072 * 1024];

// ==================== conversion kernels ====================
__global__ void conv_enc(const float* __restrict__ enc) {
    size_t idx = (size_t)blockIdx.x * 256 + threadIdx.x;
    d_enc_h[idx] = __float2half_rn(enc[idx]);
}

__device__ __forceinline__ size_t wimg_off(int n, int k, int kwc) {
    int nt = n >> 7, r = n & 127;
    int cc = k >> 6, j = k & 63;
    uint32_t byte = (uint32_t)((r << 7) + (j << 1));
    return (((size_t)(nt * kwc + cc)) << 13) + (swz(byte) >> 1);
}

__global__ void conv_all(const float* __restrict__ ws_hh, const float* __restrict__ wa_hh,
                         const float* __restrict__ wo_hh, const float* __restrict__ ws_ih,
                         const float* __restrict__ wa_ih, const float* __restrict__ wo_ih) {
    int z = blockIdx.z;
    const float* src;
    __half* img;
    int ld, off, kb;
    switch (z) {
        case 0: src = ws_hh; img = d_img_hh_s;  ld = 1024; off = 0;    kb = 10; break;
        case 1: src = wa_hh; img = d_img_hh_a;  ld = 1024; off = 0;    kb = 10; break;
        case 2: src = wo_hh; img = d_img_hh_o;  ld = 1024; off = 0;    kb = 10; break;
        case 3: src = ws_ih; img = d_img_ihE_s; ld = 3072; off = 0;    kb = 11; break;
        case 4: src = wa_ih; img = d_img_ihE_a; ld = 3072; off = 0;    kb = 11; break;
        case 5: src = wo_ih; img = d_img_ihE_o; ld = 2048; off = 0;    kb = 11; break;
        case 6: src = ws_ih; img = d_img_ihH_s; ld = 3072; off = 2048; kb = 10; break;
        default: src = wa_ih; img = d_img_ihH_a; ld = 3072; off = 2048; kb = 10; break;
    }
    size_t idx = (size_t)blockIdx.x * 256 + threadIdx.x;
    if (idx >= ((size_t)3072 << kb)) return;
    int n = (int)(idx >> kb);
    int k = (int)(idx & ((1 << kb) - 1));
    float x = src[(size_t)n * ld + off + k];
    img[wimg_off(n, k, 1 << (kb - 6))] = __float2half_rn(x);
}

// ==================== GEMM core: 128x128 tile, k64 chunks, 3-stage ====================
static constexpr int STAGE = 32768;                  // A 16K + W 16K
static constexpr int SMEM_TOTAL = 1024 + 3 * STAGE;  // 99328

__device__ __forceinline__ void load_stage(uint32_t st, const __half* __restrict__ Ah,
                                           int astride, const int* __restrict__ rowmap,
                                           int koff, const __half* __restrict__ Wchunk,
                                           int tid) {
#pragma unroll
    for (int i = 0; i < 4; i++) {
        int lin = tid + (i << 8);
        int row = lin >> 3, seg = lin & 7;
        uint32_t so = swz((uint32_t)((row << 7) + (seg << 4)));
        cpa16(st + so, Ah + (size_t)rowmap[row] * astride + koff + (seg << 3));
    }
    const char* ws = (const char*)Wchunk;
#pragma unroll
    for (int i = 0; i < 4; i++) {
        uint32_t o = (uint32_t)((tid + (i << 8)) << 4);
        cpa16(st + 16384 + o, ws + o);
    }
    asm volatile("cp.async.commit_group;" ::: "memory");
}

// C(128x128) = Arows(128 x K) * W(128 x K)^T, single-pass fp16
__device__ void tc_gemm(const __half* __restrict__ Ah, int astride, int kchunks,
                        const __half* __restrict__ Wimg,  // pre-offset to this ntile
                        const int* __restrict__ rowmap, float* __restrict__ Cmn) {
    extern __shared__ char smem[];
    uint32_t sb = smem_to_u32(smem) + 1024;
    const int tid = threadIdx.x;
    const int wid = tid >> 5;
    const int lid = tid & 31;
    const int wm = (wid >> 2) << 6;  // 0 or 64
    const int wn = (wid & 3) << 5;   // 0,32,64,96

    const int a_r = (lid & 7) | (((lid >> 3) & 1) << 3);
    const int a_kb = ((lid >> 4) & 1) << 4;
    const int w_r = (lid & 7) | (((lid >> 4) & 1) << 3);
    const int w_kb = ((lid >> 3) & 1) << 4;

    float acc[4][4][4];
#pragma unroll
    for (int i = 0; i < 4; i++)
#pragma unroll
        for (int j = 0; j < 4; j++)
#pragma unroll
            for (int q = 0; q < 4; q++) acc[i][j][q] = 0.f;

#pragma unroll
    for (int c = 0; c < 2; c++)
        if (c < kchunks)
            load_stage(sb + c * STAGE, Ah, astride, rowmap, c << 6,
                       Wimg + ((size_t)c << 13), tid);

    int stage = 0;
    for (int c = 0; c < kchunks; c++) {
        if (c + 1 < kchunks) asm volatile("cp.async.wait_group 1;" ::: "memory");
        else                 asm volatile("cp.async.wait_group 0;" ::: "memory");
        __syncthreads();
        if (c + 2 < kchunks) {
            int ns = stage + 2;
            if (ns >= 3) ns -= 3;
            load_stage(sb + ns * STAGE, Ah, astride, rowmap, (c + 2) << 6,
                       Wimg + ((size_t)(c + 2) << 13), tid);
        }
        uint32_t stA = sb + stage * STAGE;
        uint32_t stW = stA + 16384;
#pragma unroll
        for (int ks = 0; ks < 4; ks++) {
            uint32_t wf[8];
#pragma unroll
            for (int p = 0; p < 2; p++) {
                uint32_t rowb = (uint32_t)((wn + (p << 4) + w_r) << 7);
                ldm_x4(wf + (p << 2), stW + swz(rowb + (ks << 5) + w_kb));
            }
#pragma unroll
            for (int mt = 0; mt < 4; mt++) {
                uint32_t af[4];
                uint32_t rowb = (uint32_t)((wm + (mt << 4) + a_r) << 7);
                ldm_x4(af, stA + swz(rowb + (ks << 5) + a_kb));
#pragma unroll
                for (int nt = 0; nt < 4; nt++)
                    mma16816(acc[mt][nt], af, wf + (nt << 1));
            }
        }
        if (++stage >= 3) stage = 0;
    }

    // allow the dependent kernel to begin launching while we store the epilogue
    pdl_trigger();

    // epilogue
    const int mrow = lid >> 2;
    const int ncol = (lid & 3) << 1;
#pragma unroll
    for (int mt = 0; mt < 4; mt++) {
#pragma unroll
        for (int nt = 0; nt < 4; nt++) {
            float* c0 = Cmn + (size_t)(wm + (mt << 4) + mrow) * H3 + wn + (nt << 3) + ncol;
            *(float2*)c0 = make_float2(acc[mt][nt][0], acc[mt][nt][1]);
            *(float2*)(c0 + 8 * H3) = make_float2(acc[mt][nt][2], acc[mt][nt][3]);
        }
    }
}

// ==================== pre GEMM (timesteps [tbase, tbase+4)) ====================
// GI row for (t, b) = t*B + b; A row in d_enc_h for (t, b) = b*T + t
__global__ __launch_bounds__(256, 2) void pre_gemm_k(int tbase) {
    __shared__ int rowmap[128];
    int t = tbase + blockIdx.y;
    if (threadIdx.x < 128) rowmap[threadIdx.x] = threadIdx.x * T_ + t;
    __syncthreads();
    const __half* img;
    float* C;
    if (blockIdx.z == 0)      { img = d_img_ihE_s; C = d_GI_s; }
    else if (blockIdx.z == 1) { img = d_img_ihE_a; C = d_GI_a; }
    else                      { img = d_img_ihE_o; C = d_GI_o; }
    int nt = blockIdx.x;
    size_t woff = (size_t)nt * 32 * 8192;  // 32 k64-chunks per 128-col ntile
    tc_gemm(d_enc_h, E_, 32, img + woff, rowmap,
            C + ((size_t)t * B_) * H3 + nt * 128);
}

// ==================== step GEMM (PDL consumer of pointwise(t-1)) ====================
// virtual row layout in d_G (1280 rows x 3072):
//   [0,128) spk gh | [128,256) adr gh | [256,1024) oth gh |
//   [1024,1152) spk ih-state | [1152,1280) adr ih-state
__global__ __launch_bounds__(256, 2) void step_gemm_k(const int* __restrict__ dig, int t) {
    __shared__ int rowmap[128];
    int my = blockIdx.y;
    int m0 = my << 7;
    if (threadIdx.x < 128) {
        int i = threadIdx.x;
        int m = m0 + i;
        int b, role;
        if (m < 256 || m >= 1024) {
            b = i;
            int which = (my == 0) ? 0 : (my == 1) ? 1 : (my == 8) ? 1 : 0;
            role = dig[((size_t)(b * T_ + t)) * 2 + which];
        } else {
            int idx = m - 256;
            b = idx / 6;
            int k = idx % 6;
            int spk = dig[((size_t)(b * T_ + t)) * 2];
            int adr = dig[((size_t)(b * T_ + t)) * 2 + 1];
            int cnt = 0;
            role = 0;
#pragma unroll
            for (int rr = 0; rr < R_; rr++) {
                if (rr != spk && rr != adr) {
                    if (cnt == k) role = rr;
                    cnt++;
                }
            }
        }
        rowmap[i] = (b << 3) + role;
    }
    __syncthreads();
    const __half* img;
    if (my == 0)      img = d_img_hh_s;
    else if (my == 1) img = d_img_hh_a;
    else if (my < 8)  img = d_img_hh_o;
    else if (my == 8) img = d_img_ihH_s;
    else              img = d_img_ihH_a;
    // wait for predecessor (pointwise writing d_S_h) before loading S
    pdl_wait();
    int nt = blockIdx.x;
    size_t woff = (size_t)nt * 16 * 8192;  // 16 k64-chunks per ntile
    tc_gemm(d_S_h, H_, 16, img + woff, rowmap, d_G + (size_t)m0 * H3 + nt * 128);
}

// ==================== pointwise GRU update (float4, PDL both sides) ====================
__global__ __launch_bounds__(512) void gru_pointwise(
    float* __restrict__ A, const int* __restrict__ dig, int t,
    const float* __restrict__ bih_s, const float* __restrict__ bhh_s,
    const float* __restrict__ bih_a, const float* __restrict__ bhh_a,
    const float* __restrict__ bih_o, const float* __restrict__ bhh_o) {
    // let step_gemm(t+1) start its prologue while we run
    pdl_trigger();
    int i4 = blockIdx.x * 512 + threadIdx.x;  // < B*R*H/4
    int idx = i4 << 2;
    int h = idx & (H_ - 1);
    int br = idx >> 10;
    int r = br & 7, b = br >> 3;
    int spk = dig[((size_t)(b * T_ + t)) * 2];
    int adr = dig[((size_t)(b * T_ + t)) * 2 + 1];
    const float *GI, *gihs = nullptr, *bih, *bhh;
    int ghrow;
    if (r == spk) {
        ghrow = b; gihs = d_G + (size_t)(1024 + b) * H3;
        GI = d_GI_s; bih = bih_s; bhh = bhh_s;
    } else if (r == adr) {
        ghrow = 128 + b; gihs = d_G + (size_t)(1152 + b) * H3;
        GI = d_GI_a; bih = bih_a; bhh = bhh_a;
    } else {
        int k = r - (spk < r ? 1 : 0) - (adr < r ? 1 : 0);
        ghrow = 256 + b * 6 + k;
        GI = d_GI_o; bih = bih_o; bhh = bhh_o;
    }
    // wait for step_gemm(t) writes to d_G before reading
    pdl_wait();
    // t-major GI: row = t*B + b
    const float* gi = GI + ((size_t)t * B_ + b) * H3 + h;
    const float* gh = d_G + (size_t)ghrow * H3 + h;
    float4 gir = *(const float4*)(gi);
    float4 giz = *(const float4*)(gi + H_);
    float4 gin = *(const float4*)(gi + 2 * H_);
    if (gihs) {
        const float* gs = gihs + h;
        float4 s0 = *(const float4*)(gs);
        float4 s1 = *(const float4*)(gs + H_);
        float4 s2 = *(const float4*)(gs + 2 * H_);
        gir.x += s0.x; gir.y += s0.y; gir.z += s0.z; gir.w += s0.w;
        giz.x += s1.x; giz.y += s1.y; giz.z += s1.z; giz.w += s1.w;
        gin.x += s2.x; gin.y += s2.y; gin.z += s2.z; gin.w += s2.w;
    }
    float4 ghr = *(const float4*)(gh);
    float4 ghz = *(const float4*)(gh + H_);
    float4 ghn = *(const float4*)(gh + 2 * H_);
    float4 b0 = *(const float4*)(bih + h);
    float4 b1 = *(const float4*)(bih + H_ + h);
    float4 b2 = *(const float4*)(bih + 2 * H_ + h);
    float4 c0 = *(const float4*)(bhh + h);
    float4 c1 = *(const float4*)(bhh + H_ + h);
    float4 c2 = *(const float4*)(bhh + 2 * H_ + h);
    float4 hold = *(const float4*)(A + idx);
    float out[4];
    __half outh[4];
#pragma unroll
    for (int q = 0; q < 4; q++) {
        float vr = ((&gir.x)[q] + (&b0.x)[q]) + ((&ghr.x)[q] + (&c0.x)[q]);
        float vz = ((&giz.x)[q] + (&b1.x)[q]) + ((&ghz.x)[q] + (&c1.x)[q]);
        float hn = (&ghn.x)[q] + (&c2.x)[q];
        float rg = 1.f / (1.f + expf(-vr));
        float zg = 1.f / (1.f + expf(-vz));
        float ng = tanhf((&gin.x)[q] + (&b2.x)[q] + rg * hn);
        float nv = (1.f - zg) * ng + zg * (&hold.x)[q];
        out[q] = nv;
        outh[q] = __float2half_rn(nv);
    }
    *(float4*)(A + idx) = make_float4(out[0], out[1], out[2], out[3]);
    *(uint2*)(&d_S_h[idx]) = *(uint2*)outh;
}

static void* sym_addr(const void* sym) {
    void* p = nullptr;
    cudaGetSymbolAddress(&p, sym);
    return p;
}

extern "C" void kernel_launch(void* const* d_in, const int* in_sizes, int n_in,
                              void* d_out, int out_size) {
    (void)in_sizes; (void)n_in; (void)out_size;
    const float* enc    = (const float*)d_in[0];
    const int*   dig    = (const int*)d_in[1];
    const float* ws_ih  = (const float*)d_in[2];
    const float* ws_hh  = (const float*)d_in[3];
    const float* ws_bih = (const float*)d_in[4];
    const float* ws_bhh = (const float*)d_in[5];
    const float* wa_ih  = (const float*)d_in[6];
    const float* wa_hh  = (const float*)d_in[7];
    const float* wa_bih = (const float*)d_in[8];
    const float* wa_bhh = (const float*)d_in[9];
    const float* wo_ih  = (const float*)d_in[10];
    const float* wo_hh  = (const float*)d_in[11];
    const float* wo_bih = (const float*)d_in[12];
    const float* wo_bhh = (const float*)d_in[13];
    float* A = (float*)d_out;

    // one-time resources (created on the non-captured correctness call)
    static bool init = false;
    static cudaStream_t s2;                // LOW priority: precompute
    static cudaEvent_t evFork, evPre[16];
    if (!init) {
        int loPri = 0, hiPri = 0;
        cudaDeviceGetStreamPriorityRange(&loPri, &hiPri);
        cudaStreamCreateWithPriority(&s2, cudaStreamNonBlocking, loPri);
        cudaEventCreateWithFlags(&evFork, cudaEventDisableTiming);
        for (int i = 0; i < 16; i++)
            cudaEventCreateWithFlags(&evPre[i], cudaEventDisableTiming);
        cudaFuncSetAttribute(pre_gemm_k, cudaFuncAttributeMaxDynamicSharedMemorySize,
                             SMEM_TOTAL);
        cudaFuncSetAttribute(step_gemm_k, cudaFuncAttributeMaxDynamicSharedMemorySize,
                             SMEM_TOTAL);
        init = true;
    }

    cudaMemsetAsync(d_out, 0, (size_t)B_ * R_ * H_ * sizeof(float), 0);
    cudaMemsetAsync(sym_addr(d_S_h), 0, (size_t)B_ * R_ * H_ * 2, 0);

    conv_enc<<<(int)((size_t)B_ * T_ * E_ / 256), 256>>>(enc);
    conv_all<<<dim3(24576, 1, 8), 256>>>(ws_hh, wa_hh, wo_hh, ws_ih, wa_ih, wo_ih);

    // fork: 16 pre batches of 4 timesteps (288 CTAs) on low-priority stream
    cudaEventRecord(evFork, 0);
    cudaStreamWaitEvent(s2, evFork, 0);
    for (int i = 0; i < 16; i++) {
        pre_gemm_k<<<dim3(24, 4, 3), 256, SMEM_TOTAL, s2>>>(i * 4);
        cudaEventRecord(evPre[i], s2);
    }

    // PDL launch configs for the scan chain
    cudaLaunchAttribute pdlAttr[1];
    pdlAttr[0].id = cudaLaunchAttributeProgrammaticStreamSerialization;
    pdlAttr[0].val.programmaticStreamSerializationAllowed = 1;

    cudaLaunchConfig_t cfgG = {};
    cfgG.gridDim = dim3(24, 10, 1);
    cfgG.blockDim = dim3(256, 1, 1);
    cfgG.dynamicSmemBytes = SMEM_TOTAL;
    cfgG.stream = 0;
    cfgG.attrs = pdlAttr;
    cfgG.numAttrs = 1;

    cudaLaunchConfig_t cfgP = {};
    cfgP.gridDim = dim3(512, 1, 1);
    cfgP.blockDim = dim3(512, 1, 1);
    cfgP.dynamicSmemBytes = 0;
    cfgP.stream = 0;
    cfgP.attrs = pdlAttr;
    cfgP.numAttrs = 1;

    // sequential scan: step GEMM + pointwise per step, PDL-chained
    for (int t = 0; t < T_; t++) {
        cudaLaunchKernelEx(&cfgG, step_gemm_k, dig, t);
        if ((t & 3) == 0) cudaStreamWaitEvent(0, evPre[t >> 2], 0);
        cudaLaunchKernelEx(&cfgP, gru_pointwise, A, dig, t,
                           ws_bih, ws_bhh, wa_bih, wa_bhh, wo_bih, wo_bhh);
    }
}

// round 13
// speedup vs baseline: 1.2311x; 1.0665x over previous
#include <cuda_runtime.h>
#include <cuda_fp16.h>
#include <cstdint>
#include <math.h>

#define B_ 128
#define T_ 64
#define E_ 2048
#define H_ 1024
#define R_ 8
#define H3 3072

// ==================== helpers (baseline PTX only) ====================
__device__ __forceinline__ uint32_t smem_to_u32(const void* p) {
    uint32_t a;
    asm("{ .reg .u64 t; cvta.to.shared.u64 t, %1; cvt.u32.u64 %0, t; }"
        : "=r"(a) : "l"(p));
    return a;
}
__device__ __forceinline__ uint32_t swz(uint32_t b) { return b ^ ((b >> 3) & 0x70); }

__device__ __forceinline__ void cpa16(uint32_t dst, const void* src) {
    asm volatile("cp.async.cg.shared.global [%0], [%1], 16;" :: "r"(dst), "l"(src));
}
__device__ __forceinline__ void ldm_x4(uint32_t* r, uint32_t a) {
    asm volatile("ldmatrix.sync.aligned.m8n8.x4.shared.b16 {%0,%1,%2,%3}, [%4];"
                 : "=r"(r[0]), "=r"(r[1]), "=r"(r[2]), "=r"(r[3]) : "r"(a));
}
__device__ __forceinline__ void mma16816(float* c, const uint32_t* a, const uint32_t* b) {
    asm volatile(
        "mma.sync.aligned.m16n8k16.row.col.f32.f16.f16.f32 "
        "{%0,%1,%2,%3}, {%4,%5,%6,%7}, {%8,%9}, {%0,%1,%2,%3};"
        : "+f"(c[0]), "+f"(c[1]), "+f"(c[2]), "+f"(c[3])
        : "r"(a[0]), "r"(a[1]), "r"(a[2]), "r"(a[3]), "r"(b[0]), "r"(b[1]));
}
// PDL device controls (baseline PTX, sm_90+)
__device__ __forceinline__ void pdl_trigger() {
    asm volatile("griddepcontrol.launch_dependents;" ::: "memory");
}
__device__ __forceinline__ void pdl_wait() {
    asm volatile("griddepcontrol.wait;" ::: "memory");
}

// ==================== scratch (static device, allocation-free) ====================
// GI arrays are T-MAJOR: row index = t*B + b
__device__ float d_GI_s[(size_t)B_ * T_ * H3];
__device__ float d_GI_a[(size_t)B_ * T_ * H3];
__device__ float d_GI_o[(size_t)B_ * T_ * H3];
__device__ float d_G[1280 * H3];

__device__ __half d_enc_h[(size_t)B_ * T_ * E_];  // row = b*T + t (input layout)
__device__ __half d_S_h[(size_t)B_ * R_ * H_];

// W images (fp16). Per ntile (128 n-rows) per k64 chunk: a 16KB SW128 tile.
__device__ __align__(16) __half d_img_hh_s[3072 * 1024];
__device__ __align__(16) __half d_img_hh_a[3072 * 1024];
__device__ __align__(16) __half d_img_hh_o[3072 * 1024];
__device__ __align__(16) __half d_img_ihE_s[3072 * 2048];
__device__ __align__(16) __half d_img_ihE_a[3072 * 2048];
__device__ __align__(16) __half d_img_ihE_o[3072 * 2048];
__device__ __align__(16) __half d_img_ihH_s[3072 * 1024];
__device__ __align__(16) __half d_img_ihH_a[3072 * 1024];

// ==================== conversion kernels ====================
__global__ void conv_enc(const float* __restrict__ enc) {
    size_t idx = (size_t)blockIdx.x * 256 + threadIdx.x;
    d_enc_h[idx] = __float2half_rn(enc[idx]);
}

__device__ __forceinline__ size_t wimg_off(int n, int k, int kwc) {
    int nt = n >> 7, r = n & 127;
    int cc = k >> 6, j = k & 63;
    uint32_t byte = (uint32_t)((r << 7) + (j << 1));
    return (((size_t)(nt * kwc + cc)) << 13) + (swz(byte) >> 1);
}

__global__ void conv_all(const float* __restrict__ ws_hh, const float* __restrict__ wa_hh,
                         const float* __restrict__ wo_hh, const float* __restrict__ ws_ih,
                         const float* __restrict__ wa_ih, const float* __restrict__ wo_ih) {
    int z = blockIdx.z;
    const float* src;
    __half* img;
    int ld, off, kb;
    switch (z) {
        case 0: src = ws_hh; img = d_img_hh_s;  ld = 1024; off = 0;    kb = 10; break;
        case 1: src = wa_hh; img = d_img_hh_a;  ld = 1024; off = 0;    kb = 10; break;
        case 2: src = wo_hh; img = d_img_hh_o;  ld = 1024; off = 0;    kb = 10; break;
        case 3: src = ws_ih; img = d_img_ihE_s; ld = 3072; off = 0;    kb = 11; break;
        case 4: src = wa_ih; img = d_img_ihE_a; ld = 3072; off = 0;    kb = 11; break;
        case 5: src = wo_ih; img = d_img_ihE_o; ld = 2048; off = 0;    kb = 11; break;
        case 6: src = ws_ih; img = d_img_ihH_s; ld = 3072; off = 2048; kb = 10; break;
        default: src = wa_ih; img = d_img_ihH_a; ld = 3072; off = 2048; kb = 10; break;
    }
    size_t idx = (size_t)blockIdx.x * 256 + threadIdx.x;
    if (idx >= ((size_t)3072 << kb)) return;
    int n = (int)(idx >> kb);
    int k = (int)(idx & ((1 << kb) - 1));
    float x = src[(size_t)n * ld + off + k];
    img[wimg_off(n, k, 1 << (kb - 6))] = __float2half_rn(x);
}

// ==================== GEMM core: 128x128 tile, 128 threads, 64x64 warp tiles ====================
static constexpr int STAGE = 32768;                  // A 16K + W 16K
static constexpr int SMEM_TOTAL = 1024 + 3 * STAGE;  // 99328

__device__ __forceinline__ void load_stage(uint32_t st, const __half* __restrict__ Ah,
                                           int astride, const int* __restrict__ rowmap,
                                           int koff, const __half* __restrict__ Wchunk,
                                           int tid) {
#pragma unroll
    for (int i = 0; i < 8; i++) {
        int lin = tid + (i << 7);
        int row = lin >> 3, seg = lin & 7;
        uint32_t so = swz((uint32_t)((row << 7) + (seg << 4)));
        cpa16(st + so, Ah + (size_t)rowmap[row] * astride + koff + (seg << 3));
    }
    const char* ws = (const char*)Wchunk;
#pragma unroll
    for (int i = 0; i < 8; i++) {
        uint32_t o = (uint32_t)((tid + (i << 7)) << 4);
        cpa16(st + 16384 + o, ws + o);
    }
    asm volatile("cp.async.commit_group;" ::: "memory");
}

// C(128x128) = Arows(128 x K) * W(128 x K)^T, single-pass fp16
// 4 warps, warp tile 64x64 (2m x 2n warp grid): 128B smem per HMMA
__device__ void tc_gemm(const __half* __restrict__ Ah, int astride, int kchunks,
                        const __half* __restrict__ Wimg,  // pre-offset to this ntile
                        const int* __restrict__ rowmap, float* __restrict__ Cmn) {
    extern __shared__ char smem[];
    uint32_t sb = smem_to_u32(smem) + 1024;
    const int tid = threadIdx.x;   // 0..127
    const int wid = tid >> 5;      // 0..3
    const int lid = tid & 31;
    const int wm = (wid >> 1) << 6;  // 0 or 64
    const int wn = (wid & 1) << 6;   // 0 or 64

    const int a_r = (lid & 7) | (((lid >> 3) & 1) << 3);
    const int a_kb = ((lid >> 4) & 1) << 4;
    const int w_r = (lid & 7) | (((lid >> 4) & 1) << 3);
    const int w_kb = ((lid >> 3) & 1) << 4;

    float acc[4][8][4];
#pragma unroll
    for (int i = 0; i < 4; i++)
#pragma unroll
        for (int j = 0; j < 8; j++)
#pragma unroll
            for (int q = 0; q < 4; q++) acc[i][j][q] = 0.f;

#pragma unroll
    for (int c = 0; c < 2; c++)
        if (c < kchunks)
            load_stage(sb + c * STAGE, Ah, astride, rowmap, c << 6,
                       Wimg + ((size_t)c << 13), tid);

    int stage = 0;
    for (int c = 0; c < kchunks; c++) {
        if (c + 1 < kchunks) asm volatile("cp.async.wait_group 1;" ::: "memory");
        else                 asm volatile("cp.async.wait_group 0;" ::: "memory");
        __syncthreads();
        if (c + 2 < kchunks) {
            int ns = stage + 2;
            if (ns >= 3) ns -= 3;
            load_stage(sb + ns * STAGE, Ah, astride, rowmap, (c + 2) << 6,
                       Wimg + ((size_t)(c + 2) << 13), tid);
        }
        uint32_t stA = sb + stage * STAGE;
        uint32_t stW = stA + 16384;
#pragma unroll
        for (int ks = 0; ks < 4; ks++) {
            uint32_t wf[16];
#pragma unroll
            for (int p = 0; p < 4; p++) {
                uint32_t rowb = (uint32_t)((wn + (p << 4) + w_r) << 7);
                ldm_x4(wf + (p << 2), stW + swz(rowb + (ks << 5) + w_kb));
            }
#pragma unroll
            for (int mt = 0; mt < 4; mt++) {
                uint32_t af[4];
                uint32_t rowb = (uint32_t)((wm + (mt << 4) + a_r) << 7);
                ldm_x4(af, stA + swz(rowb + (ks << 5) + a_kb));
#pragma unroll
                for (int nt = 0; nt < 8; nt++)
                    mma16816(acc[mt][nt], af, wf + (nt << 1));
            }
        }
        if (++stage >= 3) stage = 0;
    }

    // allow the dependent kernel to begin launching while we store the epilogue
    pdl_trigger();

    // epilogue
    const int mrow = lid >> 2;
    const int ncol = (lid & 3) << 1;
#pragma unroll
    for (int mt = 0; mt < 4; mt++) {
#pragma unroll
        for (int nt = 0; nt < 8; nt++) {
            float* c0 = Cmn + (size_t)(wm + (mt << 4) + mrow) * H3 + wn + (nt << 3) + ncol;
            *(float2*)c0 = make_float2(acc[mt][nt][0], acc[mt][nt][1]);
            *(float2*)(c0 + 8 * H3) = make_float2(acc[mt][nt][2], acc[mt][nt][3]);
        }
    }
}

// ==================== pre GEMM (timesteps [tbase, tbase+4)) ====================
// GI row for (t, b) = t*B + b; A row in d_enc_h for (t, b) = b*T + t
__global__ __launch_bounds__(128, 2) void pre_gemm_k(int tbase) {
    __shared__ int rowmap[128];
    int t = tbase + blockIdx.y;
    rowmap[threadIdx.x] = threadIdx.x * T_ + t;
    __syncthreads();
    const __half* img;
    float* C;
    if (blockIdx.z == 0)      { img = d_img_ihE_s; C = d_GI_s; }
    else if (blockIdx.z == 1) { img = d_img_ihE_a; C = d_GI_a; }
    else                      { img = d_img_ihE_o; C = d_GI_o; }
    int nt = blockIdx.x;
    size_t woff = (size_t)nt * 32 * 8192;  // 32 k64-chunks per 128-col ntile
    tc_gemm(d_enc_h, E_, 32, img + woff, rowmap,
            C + ((size_t)t * B_) * H3 + nt * 128);
}

// ==================== step GEMM (PDL consumer of pointwise(t-1)) ====================
// virtual row layout in d_G (1280 rows x 3072):
//   [0,128) spk gh | [128,256) adr gh | [256,1024) oth gh |
//   [1024,1152) spk ih-state | [1152,1280) adr ih-state
__global__ __launch_bounds__(128, 2) void step_gemm_k(const int* __restrict__ dig, int t) {
    __shared__ int rowmap[128];
    int my = blockIdx.y;
    int m0 = my << 7;
    {
        int i = threadIdx.x;
        int m = m0 + i;
        int b, role;
        if (m < 256 || m >= 1024) {
            b = i;
            int which = (my == 0) ? 0 : (my == 1) ? 1 : (my == 8) ? 1 : 0;
            role = dig[((size_t)(b * T_ + t)) * 2 + which];
        } else {
            int idx = m - 256;
            b = idx / 6;
            int k = idx % 6;
            int spk = dig[((size_t)(b * T_ + t)) * 2];
            int adr = dig[((size_t)(b * T_ + t)) * 2 + 1];
            int cnt = 0;
            role = 0;
#pragma unroll
            for (int rr = 0; rr < R_; rr++) {
                if (rr != spk && rr != adr) {
                    if (cnt == k) role = rr;
                    cnt++;
                }
            }
        }
        rowmap[i] = (b << 3) + role;
    }
    __syncthreads();
    const __half* img;
    if (my == 0)      img = d_img_hh_s;
    else if (my == 1) img = d_img_hh_a;
    else if (my < 8)  img = d_img_hh_o;
    else if (my == 8) img = d_img_ihH_s;
    else              img = d_img_ihH_a;
    // wait for predecessor (pointwise writing d_S_h) before loading S
    pdl_wait();
    int nt = blockIdx.x;
    size_t woff = (size_t)nt * 16 * 8192;  // 16 k64-chunks per ntile
    tc_gemm(d_S_h, H_, 16, img + woff, rowmap, d_G + (size_t)m0 * H3 + nt * 128);
}

// ==================== pointwise GRU update (float4, PDL both sides) ====================
__global__ __launch_bounds__(512) void gru_pointwise(
    float* __restrict__ A, const int* __restrict__ dig, int t,
    const float* __restrict__ bih_s, const float* __restrict__ bhh_s,
    const float* __restrict__ bih_a, const float* __restrict__ bhh_a,
    const float* __restrict__ bih_o, const float* __restrict__ bhh_o) {
    // let step_gemm(t+1) start its prologue while we run
    pdl_trigger();
    int i4 = blockIdx.x * 512 + threadIdx.x;  // < B*R*H/4
    int idx = i4 << 2;
    int h = idx & (H_ - 1);
    int br = idx >> 10;
    int r = br & 7, b = br >> 3;
    int spk = dig[((size_t)(b * T_ + t)) * 2];
    int adr = dig[((size_t)(b * T_ + t)) * 2 + 1];
    const float *GI, *gihs = nullptr, *bih, *bhh;
    int ghrow;
    if (r == spk) {
        ghrow = b; gihs = d_G + (size_t)(1024 + b) * H3;
        GI = d_GI_s; bih = bih_s; bhh = bhh_s;
    } else if (r == adr) {
        ghrow = 128 + b; gihs = d_G + (size_t)(1152 + b) * H3;
        GI = d_GI_a; bih = bih_a; bhh = bhh_a;
    } else {
        int k = r - (spk < r ? 1 : 0) - (adr < r ? 1 : 0);
        ghrow = 256 + b * 6 + k;
        GI = d_GI_o; bih = bih_o; bhh = bhh_o;
    }
    // wait for step_gemm(t) writes to d_G before reading
    pdl_wait();
    // t-major GI: row = t*B + b
    const float* gi = GI + ((size_t)t * B_ + b) * H3 + h;
    const float* gh = d_G + (size_t)ghrow * H3 + h;
    float4 gir = *(const float4*)(gi);
    float4 giz = *(const float4*)(gi + H_);
    float4 gin = *(const float4*)(gi + 2 * H_);
    if (gihs) {
        const float* gs = gihs + h;
        float4 s0 = *(const float4*)(gs);
        float4 s1 = *(const float4*)(gs + H_);
        float4 s2 = *(const float4*)(gs + 2 * H_);
        gir.x += s0.x; gir.y += s0.y; gir.z += s0.z; gir.w += s0.w;
        giz.x += s1.x; giz.y += s1.y; giz.z += s1.z; giz.w += s1.w;
        gin.x += s2.x; gin.y += s2.y; gin.z += s2.z; gin.w += s2.w;
    }
    float4 ghr = *(const float4*)(gh);
    float4 ghz = *(const float4*)(gh + H_);
    float4 ghn = *(const float4*)(gh + 2 * H_);
    float4 b0 = *(const float4*)(bih + h);
    float4 b1 = *(const float4*)(bih + H_ + h);
    float4 b2 = *(const float4*)(bih + 2 * H_ + h);
    float4 c0 = *(const float4*)(bhh + h);
    float4 c1 = *(const float4*)(bhh + H_ + h);
    float4 c2 = *(const float4*)(bhh + 2 * H_ + h);
    float4 hold = *(const float4*)(A + idx);
    float out[4];
    __half outh[4];
#pragma unroll
    for (int q = 0; q < 4; q++) {
        float vr = ((&gir.x)[q] + (&b0.x)[q]) + ((&ghr.x)[q] + (&c0.x)[q]);
        float vz = ((&giz.x)[q] + (&b1.x)[q]) + ((&ghz.x)[q] + (&c1.x)[q]);
        float hn = (&ghn.x)[q] + (&c2.x)[q];
        float rg = 1.f / (1.f + expf(-vr));
        float zg = 1.f / (1.f + expf(-vz));
        float ng = tanhf((&gin.x)[q] + (&b2.x)[q] + rg * hn);
        float nv = (1.f - zg) * ng + zg * (&hold.x)[q];
        out[q] = nv;
        outh[q] = __float2half_rn(nv);
    }
    *(float4*)(A + idx) = make_float4(out[0], out[1], out[2], out[3]);
    *(uint2*)(&d_S_h[idx]) = *(uint2*)outh;
}

static void* sym_addr(const void* sym) {
    void* p = nullptr;
    cudaGetSymbolAddress(&p, sym);
    return p;
}

extern "C" void kernel_launch(void* const* d_in, const int* in_sizes, int n_in,
                              void* d_out, int out_size) {
    (void)in_sizes; (void)n_in; (void)out_size;
    const float* enc    = (const float*)d_in[0];
    const int*   dig    = (const int*)d_in[1];
    const float* ws_ih  = (const float*)d_in[2];
    const float* ws_hh  = (const float*)d_in[3];
    const float* ws_bih = (const float*)d_in[4];
    const float* ws_bhh = (const float*)d_in[5];
    const float* wa_ih  = (const float*)d_in[6];
    const float* wa_hh  = (const float*)d_in[7];
    const float* wa_bih = (const float*)d_in[8];
    const float* wa_bhh = (const float*)d_in[9];
    const float* wo_ih  = (const float*)d_in[10];
    const float* wo_hh  = (const float*)d_in[11];
    const float* wo_bih = (const float*)d_in[12];
    const float* wo_bhh = (const float*)d_in[13];
    float* A = (float*)d_out;

    // one-time resources (created on the non-captured correctness call)
    static bool init = false;
    static cudaStream_t s2;                // LOW priority: precompute
    static cudaEvent_t evFork, evPre[16];
    if (!init) {
        int loPri = 0, hiPri = 0;
        cudaDeviceGetStreamPriorityRange(&loPri, &hiPri);
        cudaStreamCreateWithPriority(&s2, cudaStreamNonBlocking, loPri);
        cudaEventCreateWithFlags(&evFork, cudaEventDisableTiming);
        for (int i = 0; i < 16; i++)
            cudaEventCreateWithFlags(&evPre[i], cudaEventDisableTiming);
        cudaFuncSetAttribute(pre_gemm_k, cudaFuncAttributeMaxDynamicSharedMemorySize,
                             SMEM_TOTAL);
        cudaFuncSetAttribute(step_gemm_k, cudaFuncAttributeMaxDynamicSharedMemorySize,
                             SMEM_TOTAL);
        init = true;
    }

    cudaMemsetAsync(d_out, 0, (size_t)B_ * R_ * H_ * sizeof(float), 0);
    cudaMemsetAsync(sym_addr(d_S_h), 0, (size_t)B_ * R_ * H_ * 2, 0);

    conv_enc<<<(int)((size_t)B_ * T_ * E_ / 256), 256>>>(enc);
    conv_all<<<dim3(24576, 1, 8), 256>>>(ws_hh, wa_hh, wo_hh, ws_ih, wa_ih, wo_ih);

    // fork: 16 pre batches of 4 timesteps (288 CTAs) on low-priority stream
    cudaEventRecord(evFork, 0);
    cudaStreamWaitEvent(s2, evFork, 0);
    for (int i = 0; i < 16; i++) {
        pre_gemm_k<<<dim3(24, 4, 3), 128, SMEM_TOTAL, s2>>>(i * 4);
        cudaEventRecord(evPre[i], s2);
    }

    // PDL launch configs for the scan chain
    cudaLaunchAttribute pdlAttr[1];
    pdlAttr[0].id = cudaLaunchAttributeProgrammaticStreamSerialization;
    pdlAttr[0].val.programmaticStreamSerializationAllowed = 1;

    cudaLaunchConfig_t cfgG = {};
    cfgG.gridDim = dim3(24, 10, 1);
    cfgG.blockDim = dim3(128, 1, 1);
    cfgG.dynamicSmemBytes = SMEM_TOTAL;
    cfgG.stream = 0;
    cfgG.attrs = pdlAttr;
    cfgG.numAttrs = 1;

    cudaLaunchConfig_t cfgP = {};
    cfgP.gridDim = dim3(512, 1, 1);
    cfgP.blockDim = dim3(512, 1, 1);
    cfgP.dynamicSmemBytes = 0;
    cfgP.stream = 0;
    cfgP.attrs = pdlAttr;
    cfgP.numAttrs = 1;

    // sequential scan: step GEMM + pointwise per step, PDL-chained
    for (int t = 0; t < T_; t++) {
        cudaLaunchKernelEx(&cfgG, step_gemm_k, dig, t);
        if ((t & 3) == 0) cudaStreamWaitEvent(0, evPre[t >> 2], 0);
        cudaLaunchKernelEx(&cfgP, gru_pointwise, A, dig, t,
                           ws_bih, ws_bhh, wa_bih, wa_bhh, wo_bih, wo_bhh);
    }
}

// round 14
// speedup vs baseline: 1.2554x; 1.0198x over previous
#include <cuda_runtime.h>
#include <cuda_fp16.h>
#include <cstdint>
#include <math.h>

#define B_ 128
#define T_ 64
#define E_ 2048
#define H_ 1024
#define R_ 8
#define H3 3072

// ==================== helpers (baseline PTX only) ====================
__device__ __forceinline__ uint32_t smem_to_u32(const void* p) {
    uint32_t a;
    asm("{ .reg .u64 t; cvta.to.shared.u64 t, %1; cvt.u32.u64 %0, t; }"
        : "=r"(a) : "l"(p));
    return a;
}
__device__ __forceinline__ uint32_t swz(uint32_t b) { return b ^ ((b >> 3) & 0x70); }

__device__ __forceinline__ void cpa16(uint32_t dst, const void* src) {
    asm volatile("cp.async.cg.shared.global [%0], [%1], 16;" :: "r"(dst), "l"(src));
}
__device__ __forceinline__ void ldm_x4(uint32_t* r, uint32_t a) {
    asm volatile("ldmatrix.sync.aligned.m8n8.x4.shared.b16 {%0,%1,%2,%3}, [%4];"
                 : "=r"(r[0]), "=r"(r[1]), "=r"(r[2]), "=r"(r[3]) : "r"(a));
}
__device__ __forceinline__ void mma16816(float* c, const uint32_t* a, const uint32_t* b) {
    asm volatile(
        "mma.sync.aligned.m16n8k16.row.col.f32.f16.f16.f32 "
        "{%0,%1,%2,%3}, {%4,%5,%6,%7}, {%8,%9}, {%0,%1,%2,%3};"
        : "+f"(c[0]), "+f"(c[1]), "+f"(c[2]), "+f"(c[3])
        : "r"(a[0]), "r"(a[1]), "r"(a[2]), "r"(a[3]), "r"(b[0]), "r"(b[1]));
}
// PDL device controls (baseline PTX, sm_90+)
__device__ __forceinline__ void pdl_trigger() {
    asm volatile("griddepcontrol.launch_dependents;" ::: "memory");
}
__device__ __forceinline__ void pdl_wait() {
    asm volatile("griddepcontrol.wait;" ::: "memory");
}
// load 4 consecutive halves -> float4
__device__ __forceinline__ float4 ld4h(const __half* p) {
    uint2 u = *(const uint2*)p;
    __half2 a = *(__half2*)&u.x, b = *(__half2*)&u.y;
    float2 fa = __half22float2(a), fb = __half22float2(b);
    return make_float4(fa.x, fa.y, fb.x, fb.y);
}

// ==================== scratch (static device, allocation-free) ====================
// Gate pre-activations stored in fp16 (error ~2^-12.6, within budget).
// GI arrays are T-MAJOR: row index = t*B + b
__device__ __half d_GI_s[(size_t)B_ * T_ * H3];
__device__ __half d_GI_a[(size_t)B_ * T_ * H3];
__device__ __half d_GI_o[(size_t)B_ * T_ * H3];
__device__ __half d_G[1280 * H3];

__device__ __half d_enc_h[(size_t)B_ * T_ * E_];  // row = b*T + t (input layout)
__device__ __half d_S_h[(size_t)B_ * R_ * H_];

// W images (fp16). Per ntile (128 n-rows) per k64 chunk: a 16KB SW128 tile.
__device__ __align__(16) __half d_img_hh_s[3072 * 1024];
__device__ __align__(16) __half d_img_hh_a[3072 * 1024];
__device__ __align__(16) __half d_img_hh_o[3072 * 1024];
__device__ __align__(16) __half d_img_ihE_s[3072 * 2048];
__device__ __align__(16) __half d_img_ihE_a[3072 * 2048];
__device__ __align__(16) __half d_img_ihE_o[3072 * 2048];
__device__ __align__(16) __half d_img_ihH_s[3072 * 1024];
__device__ __align__(16) __half d_img_ihH_a[3072 * 1024];

// ==================== conversion kernels ====================
__global__ void conv_enc(const float* __restrict__ enc) {
    size_t idx = (size_t)blockIdx.x * 256 + threadIdx.x;
    d_enc_h[idx] = __float2half_rn(enc[idx]);
}

__device__ __forceinline__ size_t wimg_off(int n, int k, int kwc) {
    int nt = n >> 7, r = n & 127;
    int cc = k >> 6, j = k & 63;
    uint32_t byte = (uint32_t)((r << 7) + (j << 1));
    return (((size_t)(nt * kwc + cc)) << 13) + (swz(byte) >> 1);
}

__global__ void conv_all(const float* __restrict__ ws_hh, const float* __restrict__ wa_hh,
                         const float* __restrict__ wo_hh, const float* __restrict__ ws_ih,
                         const float* __restrict__ wa_ih, const float* __restrict__ wo_ih) {
    int z = blockIdx.z;
    const float* src;
    __half* img;
    int ld, off, kb;
    switch (z) {
        case 0: src = ws_hh; img = d_img_hh_s;  ld = 1024; off = 0;    kb = 10; break;
        case 1: src = wa_hh; img = d_img_hh_a;  ld = 1024; off = 0;    kb = 10; break;
        case 2: src = wo_hh; img = d_img_hh_o;  ld = 1024; off = 0;    kb = 10; break;
        case 3: src = ws_ih; img = d_img_ihE_s; ld = 3072; off = 0;    kb = 11; break;
        case 4: src = wa_ih; img = d_img_ihE_a; ld = 3072; off = 0;    kb = 11; break;
        case 5: src = wo_ih; img = d_img_ihE_o; ld = 2048; off = 0;    kb = 11; break;
        case 6: src = ws_ih; img = d_img_ihH_s; ld = 3072; off = 2048; kb = 10; break;
        default: src = wa_ih; img = d_img_ihH_a; ld = 3072; off = 2048; kb = 10; break;
    }
    size_t idx = (size_t)blockIdx.x * 256 + threadIdx.x;
    if (idx >= ((size_t)3072 << kb)) return;
    int n = (int)(idx >> kb);
    int k = (int)(idx & ((1 << kb) - 1));
    float x = src[(size_t)n * ld + off + k];
    img[wimg_off(n, k, 1 << (kb - 6))] = __float2half_rn(x);
}

// ==================== GEMM core: 128x128 tile, 128 threads, 64x64 warp tiles ====================
static constexpr int STAGE = 32768;                  // A 16K + W 16K
static constexpr int SMEM_TOTAL = 1024 + 3 * STAGE;  // 99328

__device__ __forceinline__ void load_stage(uint32_t st, const __half* __restrict__ Ah,
                                           int astride, const int* __restrict__ rowmap,
                                           int koff, const __half* __restrict__ Wchunk,
                                           int tid) {
#pragma unroll
    for (int i = 0; i < 8; i++) {
        int lin = tid + (i << 7);
        int row = lin >> 3, seg = lin & 7;
        uint32_t so = swz((uint32_t)((row << 7) + (seg << 4)));
        cpa16(st + so, Ah + (size_t)rowmap[row] * astride + koff + (seg << 3));
    }
    const char* ws = (const char*)Wchunk;
#pragma unroll
    for (int i = 0; i < 8; i++) {
        uint32_t o = (uint32_t)((tid + (i << 7)) << 4);
        cpa16(st + 16384 + o, ws + o);
    }
    asm volatile("cp.async.commit_group;" ::: "memory");
}

// C(128x128) = Arows(128 x K) * W(128 x K)^T, single-pass fp16; C stored fp16
// 4 warps, warp tile 64x64 (2m x 2n warp grid): 128B smem per HMMA
__device__ void tc_gemm(const __half* __restrict__ Ah, int astride, int kchunks,
                        const __half* __restrict__ Wimg,  // pre-offset to this ntile
                        const int* __restrict__ rowmap, __half* __restrict__ Cmn) {
    extern __shared__ char smem[];
    uint32_t sb = smem_to_u32(smem) + 1024;
    const int tid = threadIdx.x;   // 0..127
    const int wid = tid >> 5;      // 0..3
    const int lid = tid & 31;
    const int wm = (wid >> 1) << 6;  // 0 or 64
    const int wn = (wid & 1) << 6;   // 0 or 64

    const int a_r = (lid & 7) | (((lid >> 3) & 1) << 3);
    const int a_kb = ((lid >> 4) & 1) << 4;
    const int w_r = (lid & 7) | (((lid >> 4) & 1) << 3);
    const int w_kb = ((lid >> 3) & 1) << 4;

    float acc[4][8][4];
#pragma unroll
    for (int i = 0; i < 4; i++)
#pragma unroll
        for (int j = 0; j < 8; j++)
#pragma unroll
            for (int q = 0; q < 4; q++) acc[i][j][q] = 0.f;

#pragma unroll
    for (int c = 0; c < 2; c++)
        if (c < kchunks)
            load_stage(sb + c * STAGE, Ah, astride, rowmap, c << 6,
                       Wimg + ((size_t)c << 13), tid);

    int stage = 0;
    for (int c = 0; c < kchunks; c++) {
        if (c + 1 < kchunks) asm volatile("cp.async.wait_group 1;" ::: "memory");
        else                 asm volatile("cp.async.wait_group 0;" ::: "memory");
        __syncthreads();
        if (c + 2 < kchunks) {
            int ns = stage + 2;
            if (ns >= 3) ns -= 3;
            load_stage(sb + ns * STAGE, Ah, astride, rowmap, (c + 2) << 6,
                       Wimg + ((size_t)(c + 2) << 13), tid);
        }
        uint32_t stA = sb + stage * STAGE;
        uint32_t stW = stA + 16384;
#pragma unroll
        for (int ks = 0; ks < 4; ks++) {
            uint32_t wf[16];
#pragma unroll
            for (int p = 0; p < 4; p++) {
                uint32_t rowb = (uint32_t)((wn + (p << 4) + w_r) << 7);
                ldm_x4(wf + (p << 2), stW + swz(rowb + (ks << 5) + w_kb));
            }
#pragma unroll
            for (int mt = 0; mt < 4; mt++) {
                uint32_t af[4];
                uint32_t rowb = (uint32_t)((wm + (mt << 4) + a_r) << 7);
                ldm_x4(af, stA + swz(rowb + (ks << 5) + a_kb));
#pragma unroll
                for (int nt = 0; nt < 8; nt++)
                    mma16816(acc[mt][nt], af, wf + (nt << 1));
            }
        }
        if (++stage >= 3) stage = 0;
    }

    // allow the dependent kernel to begin launching while we store the epilogue
    pdl_trigger();

    // epilogue (fp16 stores)
    const int mrow = lid >> 2;
    const int ncol = (lid & 3) << 1;
#pragma unroll
    for (int mt = 0; mt < 4; mt++) {
#pragma unroll
        for (int nt = 0; nt < 8; nt++) {
            __half* c0 = Cmn + (size_t)(wm + (mt << 4) + mrow) * H3 + wn + (nt << 3) + ncol;
            *(__half2*)c0 = __floats2half2_rn(acc[mt][nt][0], acc[mt][nt][1]);
            *(__half2*)(c0 + 8 * H3) = __floats2half2_rn(acc[mt][nt][2], acc[mt][nt][3]);
        }
    }
}

// ==================== pre GEMM (timesteps [tbase, tbase+4)) ====================
// GI row for (t, b) = t*B + b; A row in d_enc_h for (t, b) = b*T + t
__global__ __launch_bounds__(128, 2) void pre_gemm_k(int tbase) {
    __shared__ int rowmap[128];
    int t = tbase + blockIdx.y;
    rowmap[threadIdx.x] = threadIdx.x * T_ + t;
    __syncthreads();
    const __half* img;
    __half* C;
    if (blockIdx.z == 0)      { img = d_img_ihE_s; C = d_GI_s; }
    else if (blockIdx.z == 1) { img = d_img_ihE_a; C = d_GI_a; }
    else                      { img = d_img_ihE_o; C = d_GI_o; }
    int nt = blockIdx.x;
    size_t woff = (size_t)nt * 32 * 8192;  // 32 k64-chunks per 128-col ntile
    tc_gemm(d_enc_h, E_, 32, img + woff, rowmap,
            C + ((size_t)t * B_) * H3 + nt * 128);
}

// ==================== step GEMM (PDL consumer of pointwise(t-1)) ====================
// virtual row layout in d_G (1280 rows x 3072):
//   [0,128) spk gh | [128,256) adr gh | [256,1024) oth gh |
//   [1024,1152) spk ih-state | [1152,1280) adr ih-state
__global__ __launch_bounds__(128, 2) void step_gemm_k(const int* __restrict__ dig, int t) {
    __shared__ int rowmap[128];
    int my = blockIdx.y;
    int m0 = my << 7;
    {
        int i = threadIdx.x;
        int m = m0 + i;
        int b, role;
        if (m < 256 || m >= 1024) {
            b = i;
            int which = (my == 0) ? 0 : (my == 1) ? 1 : (my == 8) ? 1 : 0;
            role = dig[((size_t)(b * T_ + t)) * 2 + which];
        } else {
            int idx = m - 256;
            b = idx / 6;
            int k = idx % 6;
            int spk = dig[((size_t)(b * T_ + t)) * 2];
            int adr = dig[((size_t)(b * T_ + t)) * 2 + 1];
            int cnt = 0;
            role = 0;
#pragma unroll
            for (int rr = 0; rr < R_; rr++) {
                if (rr != spk && rr != adr) {
                    if (cnt == k) role = rr;
                    cnt++;
                }
            }
        }
        rowmap[i] = (b << 3) + role;
    }
    __syncthreads();
    const __half* img;
    if (my == 0)      img = d_img_hh_s;
    else if (my == 1) img = d_img_hh_a;
    else if (my < 8)  img = d_img_hh_o;
    else if (my == 8) img = d_img_ihH_s;
    else              img = d_img_ihH_a;
    // wait for predecessor (pointwise writing d_S_h) before loading S
    pdl_wait();
    int nt = blockIdx.x;
    size_t woff = (size_t)nt * 16 * 8192;  // 16 k64-chunks per ntile
    tc_gemm(d_S_h, H_, 16, img + woff, rowmap, d_G + (size_t)m0 * H3 + nt * 128);
}

// ==================== pointwise GRU update (fp16 gates, PDL both sides) ====================
__global__ __launch_bounds__(512) void gru_pointwise(
    float* __restrict__ A, const int* __restrict__ dig, int t,
    const float* __restrict__ bih_s, const float* __restrict__ bhh_s,
    const float* __restrict__ bih_a, const float* __restrict__ bhh_a,
    const float* __restrict__ bih_o, const float* __restrict__ bhh_o) {
    // let step_gemm(t+1) start its prologue while we run
    pdl_trigger();
    int i4 = blockIdx.x * 512 + threadIdx.x;  // < B*R*H/4
    int idx = i4 << 2;
    int h = idx & (H_ - 1);
    int br = idx >> 10;
    int r = br & 7, b = br >> 3;
    int spk = dig[((size_t)(b * T_ + t)) * 2];
    int adr = dig[((size_t)(b * T_ + t)) * 2 + 1];
    const __half *GI, *gihs = nullptr;
    const float *bih, *bhh;
    int ghrow;
    if (r == spk) {
        ghrow = b; gihs = d_G + (size_t)(1024 + b) * H3;
        GI = d_GI_s; bih = bih_s; bhh = bhh_s;
    } else if (r == adr) {
        ghrow = 128 + b; gihs = d_G + (size_t)(1152 + b) * H3;
        GI = d_GI_a; bih = bih_a; bhh = bhh_a;
    } else {
        int k = r - (spk < r ? 1 : 0) - (adr < r ? 1 : 0);
        ghrow = 256 + b * 6 + k;
        GI = d_GI_o; bih = bih_o; bhh = bhh_o;
    }
    // wait for step_gemm(t) writes to d_G before reading
    pdl_wait();
    // t-major GI: row = t*B + b
    const __half* gi = GI + ((size_t)t * B_ + b) * H3 + h;
    const __half* gh = d_G + (size_t)ghrow * H3 + h;
    float4 gir = ld4h(gi);
    float4 giz = ld4h(gi + H_);
    float4 gin = ld4h(gi + 2 * H_);
    if (gihs) {
        const __half* gs = gihs + h;
        float4 s0 = ld4h(gs);
        float4 s1 = ld4h(gs + H_);
        float4 s2 = ld4h(gs + 2 * H_);
        gir.x += s0.x; gir.y += s0.y; gir.z += s0.z; gir.w += s0.w;
        giz.x += s1.x; giz.y += s1.y; giz.z += s1.z; giz.w += s1.w;
        gin.x += s2.x; gin.y += s2.y; gin.z += s2.z; gin.w += s2.w;
    }
    float4 ghr = ld4h(gh);
    float4 ghz = ld4h(gh + H_);
    float4 ghn = ld4h(gh + 2 * H_);
    float4 b0 = *(const float4*)(bih + h);
    float4 b1 = *(const float4*)(bih + H_ + h);
    float4 b2 = *(const float4*)(bih + 2 * H_ + h);
    float4 c0 = *(const float4*)(bhh + h);
    float4 c1 = *(const float4*)(bhh + H_ + h);
    float4 c2 = *(const float4*)(bhh + 2 * H_ + h);
    float4 hold = *(const float4*)(A + idx);
    float out[4];
    __half outh[4];
#pragma unroll
    for (int q = 0; q < 4; q++) {
        float vr = ((&gir.x)[q] + (&b0.x)[q]) + ((&ghr.x)[q] + (&c0.x)[q]);
        float vz = ((&giz.x)[q] + (&b1.x)[q]) + ((&ghz.x)[q] + (&c1.x)[q]);
        float hn = (&ghn.x)[q] + (&c2.x)[q];
        float rg = 1.f / (1.f + expf(-vr));
        float zg = 1.f / (1.f + expf(-vz));
        float ng = tanhf((&gin.x)[q] + (&b2.x)[q] + rg * hn);
        float nv = (1.f - zg) * ng + zg * (&hold.x)[q];
        out[q] = nv;
        outh[q] = __float2half_rn(nv);
    }
    *(float4*)(A + idx) = make_float4(out[0], out[1], out[2], out[3]);
    *(uint2*)(&d_S_h[idx]) = *(uint2*)outh;
}

static void* sym_addr(const void* sym) {
    void* p = nullptr;
    cudaGetSymbolAddress(&p, sym);
    return p;
}

extern "C" void kernel_launch(void* const* d_in, const int* in_sizes, int n_in,
                              void* d_out, int out_size) {
    (void)in_sizes; (void)n_in; (void)out_size;
    const float* enc    = (const float*)d_in[0];
    const int*   dig    = (const int*)d_in[1];
    const float* ws_ih  = (const float*)d_in[2];
    const float* ws_hh  = (const float*)d_in[3];
    const float* ws_bih = (const float*)d_in[4];
    const float* ws_bhh = (const float*)d_in[5];
    const float* wa_ih  = (const float*)d_in[6];
    const float* wa_hh  = (const float*)d_in[7];
    const float* wa_bih = (const float*)d_in[8];
    const float* wa_bhh = (const float*)d_in[9];
    const float* wo_ih  = (const float*)d_in[10];
    const float* wo_hh  = (const float*)d_in[11];
    const float* wo_bih = (const float*)d_in[12];
    const float* wo_bhh = (const float*)d_in[13];
    float* A = (float*)d_out;

    // one-time resources (created on the non-captured correctness call)
    static bool init = false;
    static cudaStream_t s2;                // LOW priority: precompute
    static cudaEvent_t evFork, evPre[16];
    if (!init) {
        int loPri = 0, hiPri = 0;
        cudaDeviceGetStreamPriorityRange(&loPri, &hiPri);
        cudaStreamCreateWithPriority(&s2, cudaStreamNonBlocking, loPri);
        cudaEventCreateWithFlags(&evFork, cudaEventDisableTiming);
        for (int i = 0; i < 16; i++)
            cudaEventCreateWithFlags(&evPre[i], cudaEventDisableTiming);
        cudaFuncSetAttribute(pre_gemm_k, cudaFuncAttributeMaxDynamicSharedMemorySize,
                             SMEM_TOTAL);
        cudaFuncSetAttribute(step_gemm_k, cudaFuncAttributeMaxDynamicSharedMemorySize,
                             SMEM_TOTAL);
        init = true;
    }

    cudaMemsetAsync(d_out, 0, (size_t)B_ * R_ * H_ * sizeof(float), 0);
    cudaMemsetAsync(sym_addr(d_S_h), 0, (size_t)B_ * R_ * H_ * 2, 0);

    conv_enc<<<(int)((size_t)B_ * T_ * E_ / 256), 256>>>(enc);
    conv_all<<<dim3(24576, 1, 8), 256>>>(ws_hh, wa_hh, wo_hh, ws_ih, wa_ih, wo_ih);

    // fork: 16 pre batches of 4 timesteps (288 CTAs) on low-priority stream
    cudaEventRecord(evFork, 0);
    cudaStreamWaitEvent(s2, evFork, 0);
    for (int i = 0; i < 16; i++) {
        pre_gemm_k<<<dim3(24, 4, 3), 128, SMEM_TOTAL, s2>>>(i * 4);
        cudaEventRecord(evPre[i], s2);
    }

    // PDL launch configs for the scan chain
    cudaLaunchAttribute pdlAttr[1];
    pdlAttr[0].id = cudaLaunchAttributeProgrammaticStreamSerialization;
    pdlAttr[0].val.programmaticStreamSerializationAllowed = 1;

    cudaLaunchConfig_t cfgG = {};
    cfgG.gridDim = dim3(24, 10, 1);
    cfgG.blockDim = dim3(128, 1, 1);
    cfgG.dynamicSmemBytes = SMEM_TOTAL;
    cfgG.stream = 0;
    cfgG.attrs = pdlAttr;
    cfgG.numAttrs = 1;

    cudaLaunchConfig_t cfgP = {};
    cfgP.gridDim = dim3(512, 1, 1);
    cfgP.blockDim = dim3(512, 1, 1);
    cfgP.dynamicSmemBytes = 0;
    cfgP.stream = 0;
    cfgP.attrs = pdlAttr;
    cfgP.numAttrs = 1;

    // sequential scan: step GEMM + pointwise per step, PDL-chained
    for (int t = 0; t < T_; t++) {
        cudaLaunchKernelEx(&cfgG, step_gemm_k, dig, t);
        if ((t & 3) == 0) cudaStreamWaitEvent(0, evPre[t >> 2], 0);
        cudaLaunchKernelEx(&cfgP, gru_pointwise, A, dig, t,
                           ws_bih, ws_bhh, wa_bih, wa_bhh, wo_bih, wo_bhh);
    }
}

// round 16
// speedup vs baseline: 1.2672x; 1.0094x over previous
#include <cuda_runtime.h>
#include <cuda_fp16.h>
#include <cstdint>
#include <math.h>

#define B_ 128
#define T_ 64
#define E_ 2048
#define H_ 1024
#define R_ 8
#define H3 3072

// ==================== helpers (baseline PTX only) ====================
__device__ __forceinline__ uint32_t smem_to_u32(const void* p) {
    uint32_t a;
    asm("{ .reg .u64 t; cvta.to.shared.u64 t, %1; cvt.u32.u64 %0, t; }"
        : "=r"(a) : "l"(p));
    return a;
}
__device__ __forceinline__ uint32_t swz(uint32_t b) { return b ^ ((b >> 3) & 0x70); }

__device__ __forceinline__ void cpa16(uint32_t dst, const void* src) {
    asm volatile("cp.async.cg.shared.global [%0], [%1], 16;" :: "r"(dst), "l"(src));
}
__device__ __forceinline__ void ldm_x4(uint32_t* r, uint32_t a) {
    asm volatile("ldmatrix.sync.aligned.m8n8.x4.shared.b16 {%0,%1,%2,%3}, [%4];"
                 : "=r"(r[0]), "=r"(r[1]), "=r"(r[2]), "=r"(r[3]) : "r"(a));
}
__device__ __forceinline__ void mma16816(float* c, const uint32_t* a, const uint32_t* b) {
    asm volatile(
        "mma.sync.aligned.m16n8k16.row.col.f32.f16.f16.f32 "
        "{%0,%1,%2,%3}, {%4,%5,%6,%7}, {%8,%9}, {%0,%1,%2,%3};"
        : "+f"(c[0]), "+f"(c[1]), "+f"(c[2]), "+f"(c[3])
        : "r"(a[0]), "r"(a[1]), "r"(a[2]), "r"(a[3]), "r"(b[0]), "r"(b[1]));
}
// PDL device controls (baseline PTX, sm_90+)
__device__ __forceinline__ void pdl_trigger() {
    asm volatile("griddepcontrol.launch_dependents;" ::: "memory");
}
__device__ __forceinline__ void pdl_wait() {
    asm volatile("griddepcontrol.wait;" ::: "memory");
}
// load 4 consecutive halves -> float4
__device__ __forceinline__ float4 ld4h(const __half* p) {
    uint2 u = *(const uint2*)p;
    __half2 a = *(__half2*)&u.x, b = *(__half2*)&u.y;
    float2 fa = __half22float2(a), fb = __half22float2(b);
    return make_float4(fa.x, fa.y, fb.x, fb.y);
}

// ==================== scratch (static device, allocation-free) ====================
// Gate pre-activations in fp16, biases pre-folded (bih into GI, bhh into G gh-rows).
// GI arrays are T-MAJOR: row index = t*B + b
__device__ __half d_GI_s[(size_t)B_ * T_ * H3];
__device__ __half d_GI_a[(size_t)B_ * T_ * H3];
__device__ __half d_GI_o[(size_t)B_ * T_ * H3];
__device__ __half d_G[1280 * H3];

__device__ __half d_enc_h[(size_t)B_ * T_ * E_];  // row = b*T + t (input layout)
__device__ __half d_S_h[(size_t)B_ * R_ * H_];    // fp16-resident state

// W images (fp16). Per ntile (128 n-rows) per k64 chunk: a 16KB SW128 tile.
__device__ __align__(16) __half d_img_hh_s[3072 * 1024];
__device__ __align__(16) __half d_img_hh_a[3072 * 1024];
__device__ __align__(16) __half d_img_hh_o[3072 * 1024];
__device__ __align__(16) __half d_img_ihE_s[3072 * 2048];
__device__ __align__(16) __half d_img_ihE_a[3072 * 2048];
__device__ __align__(16) __half d_img_ihE_o[3072 * 2048];
__device__ __align__(16) __half d_img_ihH_s[3072 * 1024];
__device__ __align__(16) __half d_img_ihH_a[3072 * 1024];

// ==================== conversion kernels ====================
__global__ void conv_enc(const float* __restrict__ enc) {
    size_t idx = (size_t)blockIdx.x * 256 + threadIdx.x;
    d_enc_h[idx] = __float2half_rn(enc[idx]);
}

__device__ __forceinline__ size_t wimg_off(int n, int k, int kwc) {
    int nt = n >> 7, r = n & 127;
    int cc = k >> 6, j = k & 63;
    uint32_t byte = (uint32_t)((r << 7) + (j << 1));
    return (((size_t)(nt * kwc + cc)) << 13) + (swz(byte) >> 1);
}

__global__ void conv_all(const float* __restrict__ ws_hh, const float* __restrict__ wa_hh,
                         const float* __restrict__ wo_hh, const float* __restrict__ ws_ih,
                         const float* __restrict__ wa_ih, const float* __restrict__ wo_ih) {
    int z = blockIdx.z;
    const float* src;
    __half* img;
    int ld, off, kb;
    switch (z) {
        case 0: src = ws_hh; img = d_img_hh_s;  ld = 1024; off = 0;    kb = 10; break;
        case 1: src = wa_hh; img = d_img_hh_a;  ld = 1024; off = 0;    kb = 10; break;
        case 2: src = wo_hh; img = d_img_hh_o;  ld = 1024; off = 0;    kb = 10; break;
        case 3: src = ws_ih; img = d_img_ihE_s; ld = 3072; off = 0;    kb = 11; break;
        case 4: src = wa_ih; img = d_img_ihE_a; ld = 3072; off = 0;    kb = 11; break;
        case 5: src = wo_ih; img = d_img_ihE_o; ld = 2048; off = 0;    kb = 11; break;
        case 6: src = ws_ih; img = d_img_ihH_s; ld = 3072; off = 2048; kb = 10; break;
        default: src = wa_ih; img = d_img_ihH_a; ld = 3072; off = 2048; kb = 10; break;
    }
    size_t idx = (size_t)blockIdx.x * 256 + threadIdx.x;
    if (idx >= ((size_t)3072 << kb)) return;
    int n = (int)(idx >> kb);
    int k = (int)(idx & ((1 << kb) - 1));
    float x = src[(size_t)n * ld + off + k];
    img[wimg_off(n, k, 1 << (kb - 6))] = __float2half_rn(x);
}

// ==================== GEMM core: 128x128 tile, 128 threads, 64x64 warp tiles ====================
static constexpr int STAGE = 32768;                  // A 16K + W 16K
static constexpr int SMEM_TOTAL = 1024 + 3 * STAGE;  // 99328

__device__ __forceinline__ void load_stage(uint32_t st, const __half* __restrict__ Ah,
                                           int astride, const int* __restrict__ rowmap,
                                           int koff, const __half* __restrict__ Wchunk,
                                           int tid) {
#pragma unroll
    for (int i = 0; i < 8; i++) {
        int lin = tid + (i << 7);
        int row = lin >> 3, seg = lin & 7;
        uint32_t so = swz((uint32_t)((row << 7) + (seg << 4)));
        cpa16(st + so, Ah + (size_t)rowmap[row] * astride + koff + (seg << 3));
    }
    const char* ws = (const char*)Wchunk;
#pragma unroll
    for (int i = 0; i < 8; i++) {
        uint32_t o = (uint32_t)((tid + (i << 7)) << 4);
        cpa16(st + 16384 + o, ws + o);
    }
    asm volatile("cp.async.commit_group;" ::: "memory");
}

// C(128x128) = Arows(128 x K) * W(128 x K)^T, single-pass fp16; C stored fp16.
// bias (fp32, pre-offset to this ntile) added when non-null; accum: C += result.
__device__ void tc_gemm(const __half* __restrict__ Ah, int astride, int kchunks,
                        const __half* __restrict__ Wimg,  // pre-offset to this ntile
                        const int* __restrict__ rowmap, __half* __restrict__ Cmn,
                        const float* __restrict__ bias, bool accum) {
    extern __shared__ char smem[];
    uint32_t sb = smem_to_u32(smem) + 1024;
    const int tid = threadIdx.x;   // 0..127
    const int wid = tid >> 5;      // 0..3
    const int lid = tid & 31;
    const int wm = (wid >> 1) << 6;  // 0 or 64
    const int wn = (wid & 1) << 6;   // 0 or 64

    const int a_r = (lid & 7) | (((lid >> 3) & 1) << 3);
    const int a_kb = ((lid >> 4) & 1) << 4;
    const int w_r = (lid & 7) | (((lid >> 4) & 1) << 3);
    const int w_kb = ((lid >> 3) & 1) << 4;

    float acc[4][8][4];
#pragma unroll
    for (int i = 0; i < 4; i++)
#pragma unroll
        for (int j = 0; j < 8; j++)
#pragma unroll
            for (int q = 0; q < 4; q++) acc[i][j][q] = 0.f;

#pragma unroll
    for (int c = 0; c < 2; c++)
        if (c < kchunks)
            load_stage(sb + c * STAGE, Ah, astride, rowmap, c << 6,
                       Wimg + ((size_t)c << 13), tid);

    int stage = 0;
    for (int c = 0; c < kchunks; c++) {
        if (c + 1 < kchunks) asm volatile("cp.async.wait_group 1;" ::: "memory");
        else                 asm volatile("cp.async.wait_group 0;" ::: "memory");
        __syncthreads();
        if (c + 2 < kchunks) {
            int ns = stage + 2;
            if (ns >= 3) ns -= 3;
            load_stage(sb + ns * STAGE, Ah, astride, rowmap, (c + 2) << 6,
                       Wimg + ((size_t)(c + 2) << 13), tid);
        }
        uint32_t stA = sb + stage * STAGE;
        uint32_t stW = stA + 16384;
#pragma unroll
        for (int ks = 0; ks < 4; ks++) {
            uint32_t wf[16];
#pragma unroll
            for (int p = 0; p < 4; p++) {
                uint32_t rowb = (uint32_t)((wn + (p << 4) + w_r) << 7);
                ldm_x4(wf + (p << 2), stW + swz(rowb + (ks << 5) + w_kb));
            }
#pragma unroll
            for (int mt = 0; mt < 4; mt++) {
                uint32_t af[4];
                uint32_t rowb = (uint32_t)((wm + (mt << 4) + a_r) << 7);
                ldm_x4(af, stA + swz(rowb + (ks << 5) + a_kb));
#pragma unroll
                for (int nt = 0; nt < 8; nt++)
                    mma16816(acc[mt][nt], af, wf + (nt << 1));
            }
        }
        if (++stage >= 3) stage = 0;
    }

    // allow the dependent kernel to begin launching while we store the epilogue
    pdl_trigger();

    // epilogue (fp16 stores, optional bias fold / accumulate)
    const int mrow = lid >> 2;
    const int ncol = (lid & 3) << 1;
#pragma unroll
    for (int mt = 0; mt < 4; mt++) {
#pragma unroll
        for (int nt = 0; nt < 8; nt++) {
            __half* c0 = Cmn + (size_t)(wm + (mt << 4) + mrow) * H3 + wn + (nt << 3) + ncol;
            float bx = 0.f, by = 0.f;
            if (bias) {
                float2 bv = *(const float2*)(bias + wn + (nt << 3) + ncol);
                bx = bv.x; by = bv.y;
            }
            float a0 = acc[mt][nt][0] + bx, a1 = acc[mt][nt][1] + by;
            float a2 = acc[mt][nt][2] + bx, a3 = acc[mt][nt][3] + by;
            if (accum) {
                float2 f0 = __half22float2(*(__half2*)c0);
                float2 f1 = __half22float2(*(__half2*)(c0 + 8 * H3));
                a0 += f0.x; a1 += f0.y; a2 += f1.x; a3 += f1.y;
            }
            *(__half2*)c0 = __floats2half2_rn(a0, a1);
            *(__half2*)(c0 + 8 * H3) = __floats2half2_rn(a2, a3);
        }
    }
}

// ==================== pre GEMM (timesteps [tbase, tbase+4), K-half khalf) ====================
// GI row for (t, b) = t*B + b; A row in d_enc_h for (t, b) = b*T + t
__global__ __launch_bounds__(128, 2) void pre_gemm_k(int tbase, int khalf,
                                                     const float* __restrict__ bs,
                                                     const float* __restrict__ ba,
                                                     const float* __restrict__ bo) {
    __shared__ int rowmap[128];
    int t = tbase + blockIdx.y;
    rowmap[threadIdx.x] = threadIdx.x * T_ + t;
    __syncthreads();
    const __half* img;
    __half* C;
    const float* bias;
    if (blockIdx.z == 0)      { img = d_img_ihE_s; C = d_GI_s; bias = bs; }
    else if (blockIdx.z == 1) { img = d_img_ihE_a; C = d_GI_a; bias = ba; }
    else                      { img = d_img_ihE_o; C = d_GI_o; bias = bo; }
    int nt = blockIdx.x;
    // 16 k64-chunks per half; W chunks for this ntile start at nt*32, half at +khalf*16
    size_t woff = ((size_t)nt * 32 + (size_t)khalf * 16) * 8192;
    tc_gemm(d_enc_h + (khalf << 10), E_, 16, img + woff, rowmap,
            C + ((size_t)t * B_) * H3 + nt * 128,
            (khalf == 0) ? bias + nt * 128 : nullptr, khalf == 1);
}

// ==================== step GEMM (PDL consumer of pointwise(t-1)) ====================
// virtual row layout in d_G (1280 rows x 3072):
//   [0,128) spk gh | [128,256) adr gh | [256,1024) oth gh |
//   [1024,1152) spk ih-state | [1152,1280) adr ih-state
__global__ __launch_bounds__(128, 2) void step_gemm_k(const int* __restrict__ dig, int t,
                                                      const float* __restrict__ bhh_s,
                                                      const float* __restrict__ bhh_a,
                                                      const float* __restrict__ bhh_o) {
    __shared__ int rowmap[128];
    int my = blockIdx.y;
    int m0 = my << 7;
    {
        int i = threadIdx.x;
        int m = m0 + i;
        int b, role;
        if (m < 256 || m >= 1024) {
            b = i;
            int which = (my == 0) ? 0 : (my == 1) ? 1 : (my == 8) ? 1 : 0;
            role = dig[((size_t)(b * T_ + t)) * 2 + which];
        } else {
            int idx = m - 256;
            b = idx / 6;
            int k = idx % 6;
            int spk = dig[((size_t)(b * T_ + t)) * 2];
            int adr = dig[((size_t)(b * T_ + t)) * 2 + 1];
            int cnt = 0;
            role = 0;
#pragma unroll
            for (int rr = 0; rr < R_; rr++) {
                if (rr != spk && rr != adr) {
                    if (cnt == k) role = rr;
                    cnt++;
                }
            }
        }
        rowmap[i] = (b << 3) + role;
    }
    __syncthreads();
    const __half* img;
    const float* bias;
    if (my == 0)      { img = d_img_hh_s;  bias = bhh_s; }
    else if (my == 1) { img = d_img_hh_a;  bias = bhh_a; }
    else if (my < 8)  { img = d_img_hh_o;  bias = bhh_o; }
    else if (my == 8) { img = d_img_ihH_s; bias = nullptr; }  // state partial: no bias
    else              { img = d_img_ihH_a; bias = nullptr; }
    // wait for predecessor (pointwise writing d_S_h) before loading S
    pdl_wait();
    int nt = blockIdx.x;
    size_t woff = (size_t)nt * 16 * 8192;  // 16 k64-chunks per ntile
    tc_gemm(d_S_h, H_, 16, img + woff, rowmap, d_G + (size_t)m0 * H3 + nt * 128,
            bias ? bias + nt * 128 : nullptr, false);
}

// ==================== pointwise GRU update (fp16 gates + fp16 state) ====================
__global__ __launch_bounds__(512) void gru_pointwise(const int* __restrict__ dig, int t) {
    // let step_gemm(t+1) start its prologue while we run
    pdl_trigger();
    int i4 = blockIdx.x * 512 + threadIdx.x;  // < B*R*H/4
    int idx = i4 << 2;
    int h = idx & (H_ - 1);
    int br = idx >> 10;
    int r = br & 7, b = br >> 3;
    int spk = dig[((size_t)(b * T_ + t)) * 2];
    int adr = dig[((size_t)(b * T_ + t)) * 2 + 1];
    const __half *GI, *gihs = nullptr;
    int ghrow;
    if (r == spk) {
        ghrow = b; gihs = d_G + (size_t)(1024 + b) * H3;
        GI = d_GI_s;
    } else if (r == adr) {
        ghrow = 128 + b; gihs = d_G + (size_t)(1152 + b) * H3;
        GI = d_GI_a;
    } else {
        int k = r - (spk < r ? 1 : 0) - (adr < r ? 1 : 0);
        ghrow = 256 + b * 6 + k;
        GI = d_GI_o;
    }
    // wait for step_gemm(t) writes to d_G before reading
    pdl_wait();
    // t-major GI: row = t*B + b; biases already folded into GI and gh rows
    const __half* gi = GI + ((size_t)t * B_ + b) * H3 + h;
    const __half* gh = d_G + (size_t)ghrow * H3 + h;
    float4 gir = ld4h(gi);
    float4 giz = ld4h(gi + H_);
    float4 gin = ld4h(gi + 2 * H_);
    if (gihs) {
        const __half* gs = gihs + h;
        float4 s0 = ld4h(gs);
        float4 s1 = ld4h(gs + H_);
        float4 s2 = ld4h(gs + 2 * H_);
        gir.x += s0.x; gir.y += s0.y; gir.z += s0.z; gir.w += s0.w;
        giz.x += s1.x; giz.y += s1.y; giz.z += s1.z; giz.w += s1.w;
        gin.x += s2.x; gin.y += s2.y; gin.z += s2.z; gin.w += s2.w;
    }
    float4 ghr = ld4h(gh);
    float4 ghz = ld4h(gh + H_);
    float4 ghn = ld4h(gh + 2 * H_);
    float4 hold = ld4h(d_S_h + idx);
    __half outh[4];
#pragma unroll
    for (int q = 0; q < 4; q++) {
        float vr = (&gir.x)[q] + (&ghr.x)[q];
        float vz = (&giz.x)[q] + (&ghz.x)[q];
        float rg = 1.f / (1.f + expf(-vr));
        float zg = 1.f / (1.f + expf(-vz));
        float ng = tanhf((&gin.x)[q] + rg * (&ghn.x)[q]);
        float nv = (1.f - zg) * ng + zg * (&hold.x)[q];
        outh[q] = __float2half_rn(nv);
    }
    *(uint2*)(&d_S_h[idx]) = *(uint2*)outh;
}

// ==================== finalize: S (fp16) -> A (fp32 output) ====================
__global__ __launch_bounds__(512) void finalize_k(float* __restrict__ A) {
    int i4 = blockIdx.x * 512 + threadIdx.x;
    int idx = i4 << 2;
    float4 v = ld4h(d_S_h + idx);
    *(float4*)(A + idx) = v;
}

static void* sym_addr(const void* sym) {
    void* p = nullptr;
    cudaGetSymbolAddress(&p, sym);
    return p;
}

extern "C" void kernel_launch(void* const* d_in, const int* in_sizes, int n_in,
                              void* d_out, int out_size) {
    (void)in_sizes; (void)n_in; (void)out_size;
    const float* enc    = (const float*)d_in[0];
    const int*   dig    = (const int*)d_in[1];
    const float* ws_ih  = (const float*)d_in[2];
    const float* ws_hh  = (const float*)d_in[3];
    const float* ws_bih = (const float*)d_in[4];
    const float* ws_bhh = (const float*)d_in[5];
    const float* wa_ih  = (const float*)d_in[6];
    const float* wa_hh  = (const float*)d_in[7];
    const float* wa_bih = (const float*)d_in[8];
    const float* wa_bhh = (const float*)d_in[9];
    const float* wo_ih  = (const float*)d_in[10];
    const float* wo_hh  = (const float*)d_in[11];
    const float* wo_bih = (const float*)d_in[12];
    const float* wo_bhh = (const float*)d_in[13];
    float* A = (float*)d_out;

    // one-time resources (created on the non-captured correctness call)
    static bool init = false;
    static cudaStream_t s2;                // LOW priority: precompute
    static cudaEvent_t evFork, evPre[16];
    if (!init) {
        int loPri = 0, hiPri = 0;
        cudaDeviceGetStreamPriorityRange(&loPri, &hiPri);
        cudaStreamCreateWithPriority(&s2, cudaStreamNonBlocking, loPri);
        cudaEventCreateWithFlags(&evFork, cudaEventDisableTiming);
        for (int i = 0; i < 16; i++)
            cudaEventCreateWithFlags(&evPre[i], cudaEventDisableTiming);
        cudaFuncSetAttribute(pre_gemm_k, cudaFuncAttributeMaxDynamicSharedMemorySize,
                             SMEM_TOTAL);
        cudaFuncSetAttribute(step_gemm_k, cudaFuncAttributeMaxDynamicSharedMemorySize,
                             SMEM_TOTAL);
        init = true;
    }

    cudaMemsetAsync(sym_addr(d_S_h), 0, (size_t)B_ * R_ * H_ * 2, 0);

    conv_enc<<<(int)((size_t)B_ * T_ * E_ / 256), 256>>>(enc);
    conv_all<<<dim3(24576, 1, 8), 256>>>(ws_hh, wa_hh, wo_hh, ws_ih, wa_ih, wo_ih);

    // fork: 16 pre batches x 2 K-halves (288 CTAs, ~half-duration CTAs) on low-pri stream
    cudaEventRecord(evFork, 0);
    cudaStreamWaitEvent(s2, evFork, 0);
    for (int i = 0; i < 16; i++) {
        pre_gemm_k<<<dim3(24, 4, 3), 128, SMEM_TOTAL, s2>>>(i * 4, 0, ws_bih, wa_bih, wo_bih);
        pre_gemm_k<<<dim3(24, 4, 3), 128, SMEM_TOTAL, s2>>>(i * 4, 1, ws_bih, wa_bih, wo_bih);
        cudaEventRecord(evPre[i], s2);
    }

    // PDL launch configs for the scan chain
    cudaLaunchAttribute pdlAttr[1];
    pdlAttr[0].id = cudaLaunchAttributeProgrammaticStreamSerialization;
    pdlAttr[0].val.programmaticStreamSerializationAllowed = 1;

    cudaLaunchConfig_t cfgG = {};
    cfgG.gridDim = dim3(24, 10, 1);
    cfgG.blockDim = dim3(128, 1, 1);
    cfgG.dynamicSmemBytes = SMEM_TOTAL;
    cfgG.stream = 0;
    cfgG.attrs = pdlAttr;
    cfgG.numAttrs = 1;

    cudaLaunchConfig_t cfgP = {};
    cfgP.gridDim = dim3(512, 1, 1);
    cfgP.blockDim = dim3(512, 1, 1);
    cfgP.dynamicSmemBytes = 0;
    cfgP.stream = 0;
    cfgP.attrs = pdlAttr;
    cfgP.numAttrs = 1;

    // sequential scan: step GEMM + pointwise per step, PDL-chained
    for (int t = 0; t < T_; t++) {
        cudaLaunchKernelEx(&cfgG, step_gemm_k, dig, t, ws_bhh, wa_bhh, wo_bhh);
        if ((t & 3) == 0) cudaStreamWaitEvent(0, evPre[t >> 2], 0);
        cudaLaunchKernelEx(&cfgP, gru_pointwise, dig, t);
    }
    finalize_k<<<512, 512>>>(A);
}